// round 7
// baseline (speedup 1.0000x reference)
#include <cuda_runtime.h>
#include <cuda_fp16.h>
#include <cstdint>

#define B_  4
#define C_  512
#define CI_ 256
#define N_  4096
#define EPS_ 1e-5f
#define ZSCALE 64.0f
#define SLICES 16

// ------------------------- device scratch (no allocs) -------------------------
__device__ float pgt_buf[B_ * 3 * CI_ * N_];           // 48 MB [B, (ph|g|thT), N]
__device__ float yT_buf [B_ * CI_ * N_];               // 16 MB [B,Ci,N]
__device__ float Wy_buf [B_ * C_ * N_];                // 32 MB [B,C,N]
__device__ float Zpart_buf[B_ * SLICES * CI_ * CI_];   // 16 MB
__device__ float Zt_buf[B_ * CI_ * CI_];               //  1 MB
__device__ float Wall_buf[3 * CI_ * C_];               // 1.5 MB concat weights
__device__ float ball_buf[3 * CI_];
__device__ float bn_sum[C_];
__device__ float bn_sumsq[C_];

// ------------------------------- GEMM config ----------------------------------
#define PITCH 40                        // halves per smem row (80B) -> conflict-free
#define TILE_HALVES (128 * PITCH)       // 5120 halves
#define TILE_BYTES  (TILE_HALVES * 2)   // 10240 B
#define BUF_BYTES   (4 * TILE_BYTES)    // Ah, Al, Bh, Bl = 40960
#define SMEM_GEMM_BYTES (2 * BUF_BYTES + 1024)

__device__ __forceinline__ uint32_t smem_u32(const void* p) {
    uint32_t a;
    asm("{ .reg .u64 t; cvta.to.shared.u64 t, %1; cvt.u32.u64 %0, t; }" : "=r"(a) : "l"(p));
    return a;
}
__device__ __forceinline__ void ldm_x4(uint32_t* r, uint32_t addr) {
    asm volatile("ldmatrix.sync.aligned.m8n8.x4.shared.b16 {%0,%1,%2,%3}, [%4];"
                 : "=r"(r[0]), "=r"(r[1]), "=r"(r[2]), "=r"(r[3]) : "r"(addr));
}
__device__ __forceinline__ void mma16816(float* c, const uint32_t* a, const uint32_t* b) {
    asm volatile(
        "mma.sync.aligned.m16n8k16.row.col.f32.f16.f16.f32 "
        "{%0,%1,%2,%3}, {%4,%5,%6,%7}, {%8,%9}, {%0,%1,%2,%3};"
        : "+f"(c[0]), "+f"(c[1]), "+f"(c[2]), "+f"(c[3])
        : "r"(a[0]), "r"(a[1]), "r"(a[2]), "r"(a[3]), "r"(b[0]), "r"(b[1]));
}

// split fp32x4 -> hi/lo fp16 pairs, store to smem (lo at +TILE_HALVES)
__device__ __forceinline__ void split_store(half* base, int idx, float4 x) {
    half2 h01 = __floats2half2_rn(x.x, x.y);
    half2 h23 = __floats2half2_rn(x.z, x.w);
    float2 f01 = __half22float2(h01);
    float2 f23 = __half22float2(h23);
    half2 l01 = __floats2half2_rn(x.x - f01.x, x.y - f01.y);
    half2 l23 = __floats2half2_rn(x.z - f23.x, x.w - f23.y);
    *(half2*)&base[idx]     = h01;
    *(half2*)&base[idx + 2] = h23;
    *(half2*)&base[TILE_HALVES + idx]     = l01;
    *(half2*)&base[TILE_HALVES + idx + 2] = l23;
}
__device__ __forceinline__ void split_store1(half* base, int idx, float x) {
    const half h = __float2half_rn(x);
    base[idx] = h;
    base[TILE_HALVES + idx] = __float2half_rn(x - __half2float(h));
}

// ------------------------------------------------------------------------------
// D[M,Nt] = alpha * A[M,K] @ Bop + biasM[row] + biasN[col]
// A row-major [M,K], row stride ldA (K contiguous).
// B_KN=false: B row-major [Nt,K], stride ldB (K contiguous) -> D = A.B^T
// B_KN=true : B row-major [K,Nt], stride ldB (Nt contiguous) -> D = A.B
// BN_ACC: epilogue accumulates per-row (channel) sum/sumsq into bn_sum/bn_sumsq.
// 128x128x32 tiles, 256 threads. grid=(Nt/128, M/128, nBatch*nSlices).
// fp16x3 (hh + lh + hl), fp32 accumulate.
// ------------------------------------------------------------------------------
template <bool B_KN, bool BN_ACC>
__global__ __launch_bounds__(256, 1)
void gemm_fp16x3(const float* __restrict__ A, const float* __restrict__ Bm,
                 float* __restrict__ D,
                 const float* __restrict__ biasM, const float* __restrict__ biasN,
                 int M, int Nt, int K, int ldA, int ldB, float alpha,
                 int nSlices,
                 long sbA, long slA, long sbB, long slB, long sbD, long slD)
{
    extern __shared__ char smem[];
    half*  sh  = (half*)smem;
    float* sBM = (float*)(smem + 2 * BUF_BYTES);
    float* sBN = sBM + 128;
    const uint32_t sbu = smem_u32(sh);

    const int tid = threadIdx.x;
    const int bx = blockIdx.x, by = blockIdx.y, bz = blockIdx.z;
    const int bb = bz / nSlices;
    const int ss = bz % nSlices;
    A += bb * sbA + ss * slA + (long)(by * 128) * ldA;
    if (B_KN) Bm += bb * sbB + ss * slB + (long)(bx * 128);
    else      Bm += bb * sbB + ss * slB + (long)(bx * 128) * ldB;
    D += bb * sbD + ss * slD;

    if (tid < 128) {
        sBM[tid] = biasM ? biasM[by * 128 + tid] : 0.f;
        sBN[tid] = biasN ? biasN[bx * 128 + tid] : 0.f;
    }

    const int sf = tid & 7;       // k-chunk (4 floats) for K-contiguous loads
    const int sr = tid >> 3;      // 0..31 row base
    const int nIter = K / 32;

    // A pointers (always K-contiguous)
    const float* pA[4];
#pragma unroll
    for (int i = 0; i < 4; ++i)
        pA[i] = A + (long)(sr + 32 * i) * ldA + sf * 4;

    // B pointers
    const float* pB[4];
    if (B_KN) {
        // thread covers k = (tid>>5)+8i, n = (tid&31)+32j
#pragma unroll
        for (int i = 0; i < 4; ++i)
            pB[i] = Bm + (long)((tid >> 5) + 8 * i) * ldB + (tid & 31);
    } else {
#pragma unroll
        for (int i = 0; i < 4; ++i)
            pB[i] = Bm + (long)(sr + 32 * i) * ldB + sf * 4;
    }

    float4 ra[4];
    float4 rb[4];          // normal mode
    float  rbs[4][4];      // B_KN mode
#pragma unroll
    for (int i = 0; i < 4; ++i) {
        ra[i] = *(const float4*)pA[i]; pA[i] += 32;
        if (B_KN) {
#pragma unroll
            for (int j = 0; j < 4; ++j) rbs[i][j] = pB[i][32 * j];
            pB[i] += 32L * ldB;
        } else {
            rb[i] = *(const float4*)pB[i]; pB[i] += 32;
        }
    }
    {
        half* Ab = sh;
        half* Bb = sh + 2 * TILE_HALVES;
#pragma unroll
        for (int i = 0; i < 4; ++i) {
            split_store(Ab, (sr + 32 * i) * PITCH + sf * 4, ra[i]);
            if (B_KN) {
                const int k = (tid >> 5) + 8 * i;
#pragma unroll
                for (int j = 0; j < 4; ++j)
                    split_store1(Bb, ((tid & 31) + 32 * j) * PITCH + k, rbs[i][j]);
            } else {
                split_store(Bb, (sr + 32 * i) * PITCH + sf * 4, rb[i]);
            }
        }
    }
    __syncthreads();

    float acc[4][4][4];
#pragma unroll
    for (int mi = 0; mi < 4; ++mi)
#pragma unroll
        for (int ni = 0; ni < 4; ++ni)
#pragma unroll
            for (int q = 0; q < 4; ++q) acc[mi][ni][q] = 0.f;

    const int wid = tid >> 5, lid = tid & 31;
    const int wm = (wid >> 2) * 64;
    const int wn = (wid & 3) * 32;
    const int g = lid >> 2;
    const int t = lid & 3;

    const uint32_t laneA = (uint32_t)((lid & 15) * (PITCH * 2) + (lid >> 4) * 16);
    const uint32_t laneB = (uint32_t)((((lid >> 4) * 8) + (lid & 7)) * (PITCH * 2)
                                      + ((lid >> 3) & 1) * 16);
    const uint32_t aWarp = sbu + (uint32_t)(wm * (PITCH * 2)) + laneA;
    const uint32_t bWarp = sbu + 2 * TILE_BYTES + (uint32_t)(wn * (PITCH * 2)) + laneB;

    for (int it = 0; it < nIter; ++it) {
        const int buf = it & 1;
        const bool hasNext = (it + 1 < nIter);
        if (hasNext) {
#pragma unroll
            for (int i = 0; i < 4; ++i) {
                ra[i] = *(const float4*)pA[i]; pA[i] += 32;
                if (B_KN) {
#pragma unroll
                    for (int j = 0; j < 4; ++j) rbs[i][j] = pB[i][32 * j];
                    pB[i] += 32L * ldB;
                } else {
                    rb[i] = *(const float4*)pB[i]; pB[i] += 32;
                }
            }
        }

        const uint32_t bo = (uint32_t)(buf * BUF_BYTES);
#pragma unroll
        for (int kk = 0; kk < 2; ++kk) {
            const uint32_t ko = (uint32_t)(kk * 32);
            uint32_t ah[4][4], al[4][4];
#pragma unroll
            for (int mi = 0; mi < 4; ++mi) {
                const uint32_t addr = aWarp + bo + (uint32_t)(mi * 16 * PITCH * 2) + ko;
                ldm_x4(ah[mi], addr);
                ldm_x4(al[mi], addr + TILE_BYTES);
            }
            uint32_t bh[2][4], bl[2][4];
#pragma unroll
            for (int nb = 0; nb < 2; ++nb) {
                const uint32_t addr = bWarp + bo + (uint32_t)(nb * 16 * PITCH * 2) + ko;
                ldm_x4(bh[nb], addr);
                ldm_x4(bl[nb], addr + TILE_BYTES);
            }
#pragma unroll
            for (int mi = 0; mi < 4; ++mi)
#pragma unroll
                for (int ni = 0; ni < 4; ++ni) {
                    const uint32_t* bb  = &bh[ni >> 1][(ni & 1) * 2];
                    const uint32_t* bbl = &bl[ni >> 1][(ni & 1) * 2];
                    mma16816(acc[mi][ni], ah[mi], bb);
                    mma16816(acc[mi][ni], al[mi], bb);
                    mma16816(acc[mi][ni], ah[mi], bbl);
                }
        }

        if (hasNext) {
            half* Ab = sh + (buf ^ 1) * (BUF_BYTES / 2);   // halves
            half* Bb = Ab + 2 * TILE_HALVES;
#pragma unroll
            for (int i = 0; i < 4; ++i) {
                split_store(Ab, (sr + 32 * i) * PITCH + sf * 4, ra[i]);
                if (B_KN) {
                    const int k = (tid >> 5) + 8 * i;
#pragma unroll
                    for (int j = 0; j < 4; ++j)
                        split_store1(Bb, ((tid & 31) + 32 * j) * PITCH + k, rbs[i][j]);
                } else {
                    split_store(Bb, (sr + 32 * i) * PITCH + sf * 4, rb[i]);
                }
            }
        }
        __syncthreads();
    }

    // ---------------- epilogue ----------------
#pragma unroll
    for (int mi = 0; mi < 4; ++mi) {
        const int rowLoc = wm + mi * 16 + g;
        const int chan0 = by * 128 + rowLoc;
        const float bm0 = sBM[rowLoc], bm1 = sBM[rowLoc + 8];
        const long gr0 = (long)chan0 * Nt + bx * 128;
        const long gr1 = gr0 + 8L * Nt;
        float s0 = 0.f, q0 = 0.f, s1 = 0.f, q1 = 0.f;
#pragma unroll
        for (int ni = 0; ni < 4; ++ni) {
            const int col = wn + ni * 8 + t * 2;
            const float bn0 = sBN[col], bn1 = sBN[col + 1];
            float2 o0, o1;
            o0.x = alpha * acc[mi][ni][0] + bm0 + bn0;
            o0.y = alpha * acc[mi][ni][1] + bm0 + bn1;
            o1.x = alpha * acc[mi][ni][2] + bm1 + bn0;
            o1.y = alpha * acc[mi][ni][3] + bm1 + bn1;
            *(float2*)&D[gr0 + col] = o0;
            *(float2*)&D[gr1 + col] = o1;
            if (BN_ACC) {
                s0 += o0.x + o0.y;  q0 += o0.x * o0.x + o0.y * o0.y;
                s1 += o1.x + o1.y;  q1 += o1.x * o1.x + o1.y * o1.y;
            }
        }
        if (BN_ACC) {
            // reduce across t lanes (quad: lane = g*4 + t)
#pragma unroll
            for (int o = 1; o < 4; o <<= 1) {
                s0 += __shfl_xor_sync(0xFFFFFFFF, s0, o);
                q0 += __shfl_xor_sync(0xFFFFFFFF, q0, o);
                s1 += __shfl_xor_sync(0xFFFFFFFF, s1, o);
                q1 += __shfl_xor_sync(0xFFFFFFFF, q1, o);
            }
            if (t == 0) {
                atomicAdd(&bn_sum[chan0],       s0);
                atomicAdd(&bn_sumsq[chan0],     q0);
                atomicAdd(&bn_sum[chan0 + 8],   s1);
                atomicAdd(&bn_sumsq[chan0 + 8], q1);
            }
        }
    }
}

// ------------------------------------------------------------------------------
// prep: concat [Wph;Wg;Wth] -> Wall [3Ci,C], biases -> ball; zero BN accumulators
__global__ __launch_bounds__(256)
void prep_kernel(const float* __restrict__ Wph, const float* __restrict__ bph,
                 const float* __restrict__ Wg,  const float* __restrict__ bg,
                 const float* __restrict__ Wth, const float* __restrict__ bth,
                 float* __restrict__ W, float* __restrict__ b)
{
    const int i = blockIdx.x * 256 + threadIdx.x;   // float4 idx, 98304 total
    const int q = CI_ * C_ / 4;                     // 32768
    float4 val = (i < q) ? ((const float4*)Wph)[i]
               : (i < 2 * q) ? ((const float4*)Wg)[i - q]
                             : ((const float4*)Wth)[i - 2 * q];
    ((float4*)W)[i] = val;
    if (i < CI_)            b[i] = bph[i];
    else if (i < 2 * CI_)   b[i] = bg[i - CI_];
    else if (i < 3 * CI_)   b[i] = bth[i - 2 * CI_];
    if (i < C_) { bn_sum[i] = 0.f; bn_sumsq[i] = 0.f; }
}

// ------------------------------------------------------------------------------
// reduce split-K partials: Zt[b][i] = sum_s Zpart[(b*SLICES+s)][i]
__global__ __launch_bounds__(256)
void zreduce_kernel(const float* __restrict__ part, float* __restrict__ out)
{
    const int i = blockIdx.x * 256 + threadIdx.x;
    const int b = blockIdx.y;
    const float* p = part + (long)b * SLICES * (CI_ * CI_) + i;
    float s = 0.f;
#pragma unroll
    for (int k = 0; k < SLICES; ++k) s += p[(long)k * (CI_ * CI_)];
    out[(long)b * (CI_ * CI_) + i] = s;
}

// ------------------------------------------------------------------------------
// BN apply + affine + residual; stats from bn_sum/bn_sumsq accumulators.
__global__ __launch_bounds__(256)
void bn_apply_kernel(const float* __restrict__ Wy,
                     const float* __restrict__ v,
                     const float* __restrict__ gamma,
                     const float* __restrict__ beta,
                     float* __restrict__ out)
{
    const long idx = (long)blockIdx.x * 256 + threadIdx.x;
    const long total4 = (long)B_ * C_ * N_ / 4;
    if (idx >= total4) return;
    const int c = (int)((idx * 4 / N_) % C_);
    const float inv = 1.f / (float)(B_ * N_);
    const float mean = bn_sum[c] * inv;
    const float var  = fmaxf(bn_sumsq[c] * inv - mean * mean, 0.f);
    const float rstd = rsqrtf(var + EPS_);
    const float sc = rstd * gamma[c];
    const float sh = beta[c] - mean * sc;
    const float4 w  = ((const float4*)Wy)[idx];
    const float4 vv = ((const float4*)v)[idx];
    float4 o;
    o.x = w.x * sc + sh + vv.x;
    o.y = w.y * sc + sh + vv.y;
    o.z = w.z * sc + sh + vv.z;
    o.w = w.w * sc + sh + vv.w;
    ((float4*)out)[idx] = o;
}

// ------------------------------------------------------------------------------
#define SYM(p, s) cudaGetSymbolAddress((void**)&p, s)

extern "C" void kernel_launch(void* const* d_in, const int* in_sizes, int n_in,
                              void* d_out, int out_size)
{
    const float* v     = (const float*)d_in[0];
    const float* Wg    = (const float*)d_in[1];
    const float* bg    = (const float*)d_in[2];
    const float* Wth   = (const float*)d_in[3];
    const float* bth   = (const float*)d_in[4];
    const float* Wph   = (const float*)d_in[5];
    const float* bph   = (const float*)d_in[6];
    const float* Ww    = (const float*)d_in[7];
    const float* bw    = (const float*)d_in[8];
    const float* gamma = (const float*)d_in[9];
    const float* beta  = (const float*)d_in[10];
    float* out = (float*)d_out;

    float *pgt, *yT, *Wy, *Zp, *Zt, *Wall, *ball;
    SYM(pgt, pgt_buf);
    SYM(yT,  yT_buf);
    SYM(Wy,  Wy_buf);
    SYM(Zp,  Zpart_buf);
    SYM(Zt,  Zt_buf);
    SYM(Wall, Wall_buf);
    SYM(ball, ball_buf);

    cudaFuncSetAttribute(gemm_fp16x3<false, false>, cudaFuncAttributeMaxDynamicSharedMemorySize, SMEM_GEMM_BYTES);
    cudaFuncSetAttribute(gemm_fp16x3<true,  false>, cudaFuncAttributeMaxDynamicSharedMemorySize, SMEM_GEMM_BYTES);
    cudaFuncSetAttribute(gemm_fp16x3<true,  true >, cudaFuncAttributeMaxDynamicSharedMemorySize, SMEM_GEMM_BYTES);

    const long sV   = (long)C_ * N_;        // v batch stride
    const long sPGT = (long)3 * CI_ * N_;   // pgt batch stride
    const long sYT  = (long)CI_ * N_;
    const long sC   = (long)C_ * N_;
    const long sZ   = (long)CI_ * CI_;

    // 0) weight concat + BN accumulator zero
    prep_kernel<<<(3 * CI_ * C_ / 4) / 256, 256>>>(Wph, bph, Wg, bg, Wth, bth, Wall, ball);

    // 1) pgt[{ph|g|thT}, n] = Wall . v + ball     (B_KN: v is [C,N], N-contiguous)
    gemm_fp16x3<true, false><<<dim3(N_ / 128, (3 * CI_) / 128, B_), 256, SMEM_GEMM_BYTES>>>(
        Wall, v, pgt, ball, nullptr, 3 * CI_, N_, C_, C_, N_, 1.f,
        1, 0, 0, sV, 0, sPGT, 0);
    // 2) Zpart[z][cg,cth] = (ZSCALE/N) * sum_{m in slice} g[cg,m] ph[cth,m]
    gemm_fp16x3<false, false><<<dim3(CI_ / 128, CI_ / 128, B_ * SLICES), 256, SMEM_GEMM_BYTES>>>(
        pgt + (long)CI_ * N_, pgt, Zp, nullptr, nullptr,
        CI_, CI_, N_ / SLICES, N_, N_, ZSCALE / (float)N_,
        SLICES, sPGT, N_ / SLICES, sPGT, N_ / SLICES, SLICES * sZ, sZ);
    // 3) Zt = sum_s Zpart
    zreduce_kernel<<<dim3(sZ / 256, B_), 256>>>(Zp, Zt);
    // 4) yT[cg,n] = (1/ZSCALE) * sum_cth Zt[cg,cth] thT[cth,n]   (B_KN)
    gemm_fp16x3<true, false><<<dim3(N_ / 128, CI_ / 128, B_), 256, SMEM_GEMM_BYTES>>>(
        Zt, pgt + (long)2 * CI_ * N_, yT, nullptr, nullptr,
        CI_, N_, CI_, CI_, N_, 1.f / ZSCALE,
        1, sZ, 0, sPGT, 0, sYT, 0);
    // 5) Wy[c,n] = sum_cg Ww[c,cg] yT[cg,n] + bw   (B_KN; BN stats in epilogue)
    gemm_fp16x3<true, true><<<dim3(N_ / 128, C_ / 128, B_), 256, SMEM_GEMM_BYTES>>>(
        Ww, yT, Wy, bw, nullptr, C_, N_, CI_, CI_, N_, 1.f,
        1, 0, 0, sYT, 0, sC, 0);

    // 6) BN apply + affine + residual
    const long total4 = (long)B_ * C_ * N_ / 4;
    bn_apply_kernel<<<(int)((total4 + 255) / 256), 256>>>(Wy, v, gamma, beta, out);
}

// round 8
// speedup vs baseline: 1.1072x; 1.1072x over previous
#include <cuda_runtime.h>
#include <cuda_fp16.h>
#include <cstdint>

#define B_  4
#define C_  512
#define CI_ 256
#define N_  4096
#define EPS_ 1e-5f
#define ZSCALE 64.0f
#define SLICES 16

// ------------------------- device scratch (no allocs) -------------------------
__device__ float vT_buf[B_ * N_ * C_];                 // 32 MB [B,N,C]
__device__ float th_buf[B_ * N_ * CI_];                // 16 MB [B,N,Ci]
__device__ float ph_buf[B_ * CI_ * N_];                // 16 MB [B,Ci,N]
__device__ float g_buf [B_ * CI_ * N_];                // 16 MB [B,Ci,N]
__device__ float y_buf [B_ * N_ * CI_];                // 16 MB [B,N,Ci]
__device__ float Wy_buf[B_ * C_ * N_];                 // 32 MB [B,C,N]
__device__ float Zt_buf[B_ * CI_ * CI_];               //  1 MB [B,cg,cth]
__device__ float bn_sum[C_];
__device__ float bn_sumsq[C_];

// ------------------------------- GEMM config ----------------------------------
#define PITCH 40                        // halves per smem row (80B) -> conflict-free
#define TILE_HALVES (128 * PITCH)       // 5120 halves
#define TILE_BYTES  (TILE_HALVES * 2)   // 10240 B
#define BUF_BYTES   (4 * TILE_BYTES)    // Ah, Al, Bh, Bl = 40960
#define SMEM_GEMM_BYTES (2 * BUF_BYTES + 1024)

__device__ __forceinline__ uint32_t smem_u32(const void* p) {
    uint32_t a;
    asm("{ .reg .u64 t; cvta.to.shared.u64 t, %1; cvt.u32.u64 %0, t; }" : "=r"(a) : "l"(p));
    return a;
}
__device__ __forceinline__ void ldm_x4(uint32_t* r, uint32_t addr) {
    asm volatile("ldmatrix.sync.aligned.m8n8.x4.shared.b16 {%0,%1,%2,%3}, [%4];"
                 : "=r"(r[0]), "=r"(r[1]), "=r"(r[2]), "=r"(r[3]) : "r"(addr));
}
__device__ __forceinline__ void mma16816(float* c, const uint32_t* a, const uint32_t* b) {
    asm volatile(
        "mma.sync.aligned.m16n8k16.row.col.f32.f16.f16.f32 "
        "{%0,%1,%2,%3}, {%4,%5,%6,%7}, {%8,%9}, {%0,%1,%2,%3};"
        : "+f"(c[0]), "+f"(c[1]), "+f"(c[2]), "+f"(c[3])
        : "r"(a[0]), "r"(a[1]), "r"(a[2]), "r"(a[3]), "r"(b[0]), "r"(b[1]));
}

// split fp32x4 -> hi/lo fp16 pairs, store to smem (lo at +TILE_HALVES)
__device__ __forceinline__ void split_store(half* base, int idx, float4 x) {
    half2 h01 = __floats2half2_rn(x.x, x.y);
    half2 h23 = __floats2half2_rn(x.z, x.w);
    float2 f01 = __half22float2(h01);
    float2 f23 = __half22float2(h23);
    half2 l01 = __floats2half2_rn(x.x - f01.x, x.y - f01.y);
    half2 l23 = __floats2half2_rn(x.z - f23.x, x.w - f23.y);
    *(half2*)&base[idx]     = h01;
    *(half2*)&base[idx + 2] = h23;
    *(half2*)&base[TILE_HALVES + idx]     = l01;
    *(half2*)&base[TILE_HALVES + idx + 2] = l23;
}

// ------------------------------------------------------------------------------
// D[M,Nt] = alpha * A[M,K] @ B[Nt,K]^T + biasM[row] + biasN[col]
// A, B row-major, row strides ldA/ldB (K contiguous). 128x128x32 tiles, 256 thr.
// grid = (Nt/128, M/128, nBatch*nSlices); per-z: X += b*sbX + s*slX.
// BN_ACC: accumulate per-row sum/sumsq into bn_sum/bn_sumsq (atomics).
// ATOMIC_OUT: atomicAdd into D (split-K reduction); biases must be null.
// fp16x3 (hh + lh + hl), fp32 accumulate.
// ------------------------------------------------------------------------------
template <bool BN_ACC, bool ATOMIC_OUT>
__global__ __launch_bounds__(256, 1)
void gemm_fp16x3(const float* __restrict__ A, const float* __restrict__ Bm,
                 float* __restrict__ D,
                 const float* __restrict__ biasM, const float* __restrict__ biasN,
                 int M, int Nt, int K, int ldA, int ldB, float alpha,
                 int nSlices,
                 long sbA, long slA, long sbB, long slB, long sbD, long slD)
{
    extern __shared__ char smem[];
    half*  sh  = (half*)smem;
    float* sBM = (float*)(smem + 2 * BUF_BYTES);
    float* sBN = sBM + 128;
    const uint32_t sbu = smem_u32(sh);

    const int tid = threadIdx.x;
    const int bx = blockIdx.x, by = blockIdx.y, bz = blockIdx.z;
    const int bb = bz / nSlices;
    const int ss = bz % nSlices;
    A  += bb * sbA + ss * slA + (long)(by * 128) * ldA;
    Bm += bb * sbB + ss * slB + (long)(bx * 128) * ldB;
    D  += bb * sbD + ss * slD;

    if (tid < 128) {
        sBM[tid] = biasM ? biasM[by * 128 + tid] : 0.f;
        sBN[tid] = biasN ? biasN[bx * 128 + tid] : 0.f;
    }

    const int sf = tid & 7;       // k-chunk (4 floats)
    const int sr = tid >> 3;      // 0..31 (row base)
    const int nIter = K / 32;

    const float* pA[4];
    const float* pB[4];
#pragma unroll
    for (int i = 0; i < 4; ++i) {
        pA[i] = A  + (long)(sr + 32 * i) * ldA + sf * 4;
        pB[i] = Bm + (long)(sr + 32 * i) * ldB + sf * 4;
    }

    float4 ra[4], rb[4];
#pragma unroll
    for (int i = 0; i < 4; ++i) {
        ra[i] = *(const float4*)pA[i]; pA[i] += 32;
        rb[i] = *(const float4*)pB[i]; pB[i] += 32;
    }
    {
        half* Ab = sh;
        half* Bb = sh + 2 * TILE_HALVES;
#pragma unroll
        for (int i = 0; i < 4; ++i) {
            const int idx = (sr + 32 * i) * PITCH + sf * 4;
            split_store(Ab, idx, ra[i]);
            split_store(Bb, idx, rb[i]);
        }
    }
    __syncthreads();

    float acc[4][4][4];
#pragma unroll
    for (int mi = 0; mi < 4; ++mi)
#pragma unroll
        for (int ni = 0; ni < 4; ++ni)
#pragma unroll
            for (int q = 0; q < 4; ++q) acc[mi][ni][q] = 0.f;

    const int wid = tid >> 5, lid = tid & 31;
    const int wm = (wid >> 2) * 64;
    const int wn = (wid & 3) * 32;
    const int g = lid >> 2;
    const int t = lid & 3;

    const uint32_t laneA = (uint32_t)((lid & 15) * (PITCH * 2) + (lid >> 4) * 16);
    const uint32_t laneB = (uint32_t)((((lid >> 4) * 8) + (lid & 7)) * (PITCH * 2)
                                      + ((lid >> 3) & 1) * 16);
    const uint32_t aWarp = sbu + (uint32_t)(wm * (PITCH * 2)) + laneA;
    const uint32_t bWarp = sbu + 2 * TILE_BYTES + (uint32_t)(wn * (PITCH * 2)) + laneB;

    for (int it = 0; it < nIter; ++it) {
        const int buf = it & 1;
        const bool hasNext = (it + 1 < nIter);
        if (hasNext) {
#pragma unroll
            for (int i = 0; i < 4; ++i) {
                ra[i] = *(const float4*)pA[i]; pA[i] += 32;
                rb[i] = *(const float4*)pB[i]; pB[i] += 32;
            }
        }

        const uint32_t bo = (uint32_t)(buf * BUF_BYTES);
#pragma unroll
        for (int kk = 0; kk < 2; ++kk) {
            const uint32_t ko = (uint32_t)(kk * 32);
            uint32_t ah[4][4], al[4][4];
#pragma unroll
            for (int mi = 0; mi < 4; ++mi) {
                const uint32_t addr = aWarp + bo + (uint32_t)(mi * 16 * PITCH * 2) + ko;
                ldm_x4(ah[mi], addr);
                ldm_x4(al[mi], addr + TILE_BYTES);
            }
            uint32_t bh[2][4], bl[2][4];
#pragma unroll
            for (int nb = 0; nb < 2; ++nb) {
                const uint32_t addr = bWarp + bo + (uint32_t)(nb * 16 * PITCH * 2) + ko;
                ldm_x4(bh[nb], addr);
                ldm_x4(bl[nb], addr + TILE_BYTES);
            }
#pragma unroll
            for (int mi = 0; mi < 4; ++mi)
#pragma unroll
                for (int ni = 0; ni < 4; ++ni) {
                    const uint32_t* bb  = &bh[ni >> 1][(ni & 1) * 2];
                    const uint32_t* bbl = &bl[ni >> 1][(ni & 1) * 2];
                    mma16816(acc[mi][ni], ah[mi], bb);
                    mma16816(acc[mi][ni], al[mi], bb);
                    mma16816(acc[mi][ni], ah[mi], bbl);
                }
        }

        if (hasNext) {
            half* Ab = sh + (buf ^ 1) * (BUF_BYTES / 2);   // halves offset
            half* Bb = Ab + 2 * TILE_HALVES;
#pragma unroll
            for (int i = 0; i < 4; ++i) {
                const int idx = (sr + 32 * i) * PITCH + sf * 4;
                split_store(Ab, idx, ra[i]);
                split_store(Bb, idx, rb[i]);
            }
        }
        __syncthreads();
    }

    // ---------------- epilogue ----------------
#pragma unroll
    for (int mi = 0; mi < 4; ++mi) {
        const int rowLoc = wm + mi * 16 + g;
        const int chan0 = by * 128 + rowLoc;
        const float bm0 = sBM[rowLoc], bm1 = sBM[rowLoc + 8];
        const long gr0 = (long)chan0 * Nt + bx * 128;
        const long gr1 = gr0 + 8L * Nt;
        float s0 = 0.f, q0 = 0.f, s1 = 0.f, q1 = 0.f;
#pragma unroll
        for (int ni = 0; ni < 4; ++ni) {
            const int col = wn + ni * 8 + t * 2;
            const float bn0 = sBN[col], bn1 = sBN[col + 1];
            float2 o0, o1;
            o0.x = alpha * acc[mi][ni][0] + bm0 + bn0;
            o0.y = alpha * acc[mi][ni][1] + bm0 + bn1;
            o1.x = alpha * acc[mi][ni][2] + bm1 + bn0;
            o1.y = alpha * acc[mi][ni][3] + bm1 + bn1;
            if (ATOMIC_OUT) {
                atomicAdd(&D[gr0 + col],     o0.x);
                atomicAdd(&D[gr0 + col + 1], o0.y);
                atomicAdd(&D[gr1 + col],     o1.x);
                atomicAdd(&D[gr1 + col + 1], o1.y);
            } else {
                *(float2*)&D[gr0 + col] = o0;
                *(float2*)&D[gr1 + col] = o1;
            }
            if (BN_ACC) {
                s0 += o0.x + o0.y;  q0 += o0.x * o0.x + o0.y * o0.y;
                s1 += o1.x + o1.y;  q1 += o1.x * o1.x + o1.y * o1.y;
            }
        }
        if (BN_ACC) {
#pragma unroll
            for (int o = 1; o < 4; o <<= 1) {
                s0 += __shfl_xor_sync(0xFFFFFFFF, s0, o);
                q0 += __shfl_xor_sync(0xFFFFFFFF, q0, o);
                s1 += __shfl_xor_sync(0xFFFFFFFF, s1, o);
                q1 += __shfl_xor_sync(0xFFFFFFFF, q1, o);
            }
            if (t == 0) {
                atomicAdd(&bn_sum[chan0],       s0);
                atomicAdd(&bn_sumsq[chan0],     q0);
                atomicAdd(&bn_sum[chan0 + 8],   s1);
                atomicAdd(&bn_sumsq[chan0 + 8], q1);
            }
        }
    }
}

// ------------------------------------------------------------------------------
// v [B,C,N] -> vT [B,N,C]
__global__ __launch_bounds__(256)
void transpose_kernel(const float* __restrict__ v, float* __restrict__ o)
{
    __shared__ float t[32][33];
    const int b = blockIdx.z;
    const int n0 = blockIdx.x * 32, c0 = blockIdx.y * 32;
    const int tx = threadIdx.x, ty = threadIdx.y;   // 32 x 8
#pragma unroll
    for (int i = 0; i < 4; ++i)
        t[ty + 8 * i][tx] = v[((long)b * C_ + c0 + ty + 8 * i) * N_ + n0 + tx];
    __syncthreads();
#pragma unroll
    for (int i = 0; i < 4; ++i)
        o[((long)b * N_ + n0 + ty + 8 * i) * C_ + c0 + tx] = t[tx][ty + 8 * i];
}

// ------------------------------------------------------------------------------
// zero Zt accumulator and BN accumulators (runs first every call)
__global__ __launch_bounds__(256)
void zero_kernel(float* __restrict__ Zt)
{
    const int i = blockIdx.x * 256 + threadIdx.x;   // 0 .. B*CI*CI-1
    Zt[i] = 0.f;
    if (i < C_) { bn_sum[i] = 0.f; bn_sumsq[i] = 0.f; }
}

// ------------------------------------------------------------------------------
// BN apply + affine + residual; stats from bn_sum/bn_sumsq accumulators.
__global__ __launch_bounds__(256)
void bn_apply_kernel(const float* __restrict__ Wy,
                     const float* __restrict__ v,
                     const float* __restrict__ gamma,
                     const float* __restrict__ beta,
                     float* __restrict__ out)
{
    const long idx = (long)blockIdx.x * 256 + threadIdx.x;
    const long total4 = (long)B_ * C_ * N_ / 4;
    if (idx >= total4) return;
    const int c = (int)((idx * 4 / N_) % C_);
    const float inv = 1.f / (float)(B_ * N_);
    const float mean = bn_sum[c] * inv;
    const float var  = fmaxf(bn_sumsq[c] * inv - mean * mean, 0.f);
    const float rstd = rsqrtf(var + EPS_);
    const float sc = rstd * gamma[c];
    const float sh = beta[c] - mean * sc;
    const float4 w  = ((const float4*)Wy)[idx];
    const float4 vv = ((const float4*)v)[idx];
    float4 o;
    o.x = w.x * sc + sh + vv.x;
    o.y = w.y * sc + sh + vv.y;
    o.z = w.z * sc + sh + vv.z;
    o.w = w.w * sc + sh + vv.w;
    ((float4*)out)[idx] = o;
}

// ------------------------------------------------------------------------------
#define SYM(p, s) cudaGetSymbolAddress((void**)&p, s)

extern "C" void kernel_launch(void* const* d_in, const int* in_sizes, int n_in,
                              void* d_out, int out_size)
{
    const float* v     = (const float*)d_in[0];
    const float* Wg    = (const float*)d_in[1];
    const float* bg    = (const float*)d_in[2];
    const float* Wth   = (const float*)d_in[3];
    const float* bth   = (const float*)d_in[4];
    const float* Wph   = (const float*)d_in[5];
    const float* bph   = (const float*)d_in[6];
    const float* Ww    = (const float*)d_in[7];
    const float* bw    = (const float*)d_in[8];
    const float* gamma = (const float*)d_in[9];
    const float* beta  = (const float*)d_in[10];
    float* out = (float*)d_out;

    float *vT, *th, *ph, *g, *y, *Wy, *Zt;
    SYM(vT, vT_buf);
    SYM(th, th_buf);
    SYM(ph, ph_buf);
    SYM(g,  g_buf);
    SYM(y,  y_buf);
    SYM(Wy, Wy_buf);
    SYM(Zt, Zt_buf);

    cudaFuncSetAttribute(gemm_fp16x3<false, false>, cudaFuncAttributeMaxDynamicSharedMemorySize, SMEM_GEMM_BYTES);
    cudaFuncSetAttribute(gemm_fp16x3<false, true >, cudaFuncAttributeMaxDynamicSharedMemorySize, SMEM_GEMM_BYTES);
    cudaFuncSetAttribute(gemm_fp16x3<true,  false>, cudaFuncAttributeMaxDynamicSharedMemorySize, SMEM_GEMM_BYTES);

    const long sVT = (long)N_ * C_;    // vT batch stride
    const long sNC = (long)N_ * CI_;   // [N,Ci]
    const long sCN = (long)CI_ * N_;   // [Ci,N]
    const long sC  = (long)C_ * N_;    // [C,N]
    const long sZ  = (long)CI_ * CI_;  // 65536

    // 0) zero Zt + BN accumulators; transpose v -> vT
    zero_kernel<<<(B_ * CI_ * CI_) / 256, 256>>>(Zt);
    transpose_kernel<<<dim3(N_ / 32, C_ / 32, B_), dim3(32, 8)>>>(v, vT);

    // 1) ph[ci,n] = Wph[ci,:].vT[n,:] + bph[ci]     (biasM)
    gemm_fp16x3<false, false><<<dim3(N_ / 128, CI_ / 128, B_), 256, SMEM_GEMM_BYTES>>>(
        Wph, vT, ph, bph, nullptr, CI_, N_, C_, C_, C_, 1.f,
        1, 0, 0, sVT, 0, sCN, 0);
    // 2) g[ci,n] = Wg[ci,:].vT[n,:] + bg[ci]
    gemm_fp16x3<false, false><<<dim3(N_ / 128, CI_ / 128, B_), 256, SMEM_GEMM_BYTES>>>(
        Wg, vT, g, bg, nullptr, CI_, N_, C_, C_, C_, 1.f,
        1, 0, 0, sVT, 0, sCN, 0);
    // 3) Zt[b][cg,cth] += (ZSCALE/N) * sum_{m in slice} g[cg,m] ph[cth,m]
    //    split-K 16 slices, atomic reduction into Zt (slD = 0)
    gemm_fp16x3<false, true><<<dim3(CI_ / 128, CI_ / 128, B_ * SLICES), 256, SMEM_GEMM_BYTES>>>(
        g, ph, Zt, nullptr, nullptr, CI_, CI_, N_ / SLICES, N_, N_, ZSCALE / (float)N_,
        SLICES, sCN, N_ / SLICES, sCN, N_ / SLICES, sZ, 0);
    // 4) th[n,cth] = vT[n,:].Wth[cth,:] + bth       (biasN)
    gemm_fp16x3<false, false><<<dim3(CI_ / 128, N_ / 128, B_), 256, SMEM_GEMM_BYTES>>>(
        vT, Wth, th, nullptr, bth, N_, CI_, C_, C_, C_, 1.f,
        1, sVT, 0, 0, 0, sNC, 0);
    // 5) y[n,cg] = (1/ZSCALE) * th[n,:].Zt[cg,:]
    gemm_fp16x3<false, false><<<dim3(CI_ / 128, N_ / 128, B_), 256, SMEM_GEMM_BYTES>>>(
        th, Zt, y, nullptr, nullptr, N_, CI_, CI_, CI_, CI_, 1.f / ZSCALE,
        1, sNC, 0, sZ, 0, sNC, 0);
    // 6) Wy[c,n] = Ww[c,:].y[n,:] + bw              (biasM; BN stats in epilogue)
    gemm_fp16x3<true, false><<<dim3(N_ / 128, C_ / 128, B_), 256, SMEM_GEMM_BYTES>>>(
        Ww, y, Wy, bw, nullptr, C_, N_, CI_, CI_, CI_, 1.f,
        1, 0, 0, sNC, 0, sC, 0);

    // 7) BN apply + affine + residual
    const long total4 = (long)B_ * C_ * N_ / 4;
    bn_apply_kernel<<<(int)((total4 + 255) / 256), 256>>>(Wy, v, gamma, beta, out);
}

// round 9
// speedup vs baseline: 1.1124x; 1.0047x over previous
#include <cuda_runtime.h>
#include <cuda_fp16.h>
#include <cstdint>

#define B_  4
#define C_  512
#define CI_ 256
#define N_  4096
#define EPS_ 1e-5f
#define ZSCALE 64.0f
#define SLICES 16

// ------------------------- device scratch (no allocs) -------------------------
__device__ float vT_buf[B_ * N_ * C_];                 // 32 MB [B,N,C]
__device__ float th_buf[B_ * N_ * CI_];                // 16 MB [B,N,Ci]
__device__ float ph_buf[B_ * CI_ * N_];                // 16 MB [B,Ci,N]
__device__ float g_buf [B_ * CI_ * N_];                // 16 MB [B,Ci,N]
__device__ float y_buf [B_ * N_ * CI_];                // 16 MB [B,N,Ci]
__device__ float Wy_buf[B_ * C_ * N_];                 // 32 MB [B,C,N]
__device__ float Zt_buf[B_ * CI_ * CI_];               //  1 MB [B,cg,cth]
__device__ float bn_sum[C_];
__device__ float bn_sumsq[C_];

// ------------------------------- GEMM config ----------------------------------
#define PITCH 40                        // halves per smem row (80B) -> conflict-free
#define TILE_HALVES (128 * PITCH)       // 5120 halves
#define TILE_BYTES  (TILE_HALVES * 2)   // 10240 B
#define BUF_BYTES   (4 * TILE_BYTES)    // Ah, Al, Bh, Bl = 40960
#define SMEM_GEMM_BYTES (2 * BUF_BYTES + 1024)

__device__ __forceinline__ uint32_t smem_u32(const void* p) {
    uint32_t a;
    asm("{ .reg .u64 t; cvta.to.shared.u64 t, %1; cvt.u32.u64 %0, t; }" : "=r"(a) : "l"(p));
    return a;
}
__device__ __forceinline__ void ldm_x4(uint32_t* r, uint32_t addr) {
    asm volatile("ldmatrix.sync.aligned.m8n8.x4.shared.b16 {%0,%1,%2,%3}, [%4];"
                 : "=r"(r[0]), "=r"(r[1]), "=r"(r[2]), "=r"(r[3]) : "r"(addr));
}
__device__ __forceinline__ void mma16816(float* c, const uint32_t* a, const uint32_t* b) {
    asm volatile(
        "mma.sync.aligned.m16n8k16.row.col.f32.f16.f16.f32 "
        "{%0,%1,%2,%3}, {%4,%5,%6,%7}, {%8,%9}, {%0,%1,%2,%3};"
        : "+f"(c[0]), "+f"(c[1]), "+f"(c[2]), "+f"(c[3])
        : "r"(a[0]), "r"(a[1]), "r"(a[2]), "r"(a[3]), "r"(b[0]), "r"(b[1]));
}

// split fp32x4 -> hi/lo fp16 pairs, store to smem (lo at +TILE_HALVES)
__device__ __forceinline__ void split_store(half* base, int idx, float4 x) {
    half2 h01 = __floats2half2_rn(x.x, x.y);
    half2 h23 = __floats2half2_rn(x.z, x.w);
    float2 f01 = __half22float2(h01);
    float2 f23 = __half22float2(h23);
    half2 l01 = __floats2half2_rn(x.x - f01.x, x.y - f01.y);
    half2 l23 = __floats2half2_rn(x.z - f23.x, x.w - f23.y);
    *(half2*)&base[idx]     = h01;
    *(half2*)&base[idx + 2] = h23;
    *(half2*)&base[TILE_HALVES + idx]     = l01;
    *(half2*)&base[TILE_HALVES + idx + 2] = l23;
}

// ------------------------------------------------------------------------------
// D[M,Nt] = alpha * A[M,K] @ B[Nt,K]^T + biasM[row] + biasN[col]
// A, B row-major, row strides ldA/ldB (K contiguous). 128x128x32 tiles, 256 thr.
// grid = (Nt/128, M/128, nBatch*nSlices); per-z: X += b*sbX + s*slX.
// BN_ACC: accumulate per-row sum/sumsq into bn_sum/bn_sumsq (atomics).
// ATOMIC_OUT: atomicAdd into D (split-K reduction); biases must be null.
// fp16x3 (hh + lh + hl), fp32 accumulate. MMA issue is reordered into three
// passes (all hh, all lh, all hl) so consecutive tensor ops never share an
// accumulator (RAW distance = 16 MMAs).
// ------------------------------------------------------------------------------
template <bool BN_ACC, bool ATOMIC_OUT>
__global__ __launch_bounds__(256, 1)
void gemm_fp16x3(const float* __restrict__ A, const float* __restrict__ Bm,
                 float* __restrict__ D,
                 const float* __restrict__ biasM, const float* __restrict__ biasN,
                 int M, int Nt, int K, int ldA, int ldB, float alpha,
                 int nSlices,
                 long sbA, long slA, long sbB, long slB, long sbD, long slD)
{
    extern __shared__ char smem[];
    half*  sh  = (half*)smem;
    float* sBM = (float*)(smem + 2 * BUF_BYTES);
    float* sBN = sBM + 128;
    const uint32_t sbu = smem_u32(sh);

    const int tid = threadIdx.x;
    const int bx = blockIdx.x, by = blockIdx.y, bz = blockIdx.z;
    const int bb = bz / nSlices;
    const int ss = bz % nSlices;
    A  += bb * sbA + ss * slA + (long)(by * 128) * ldA;
    Bm += bb * sbB + ss * slB + (long)(bx * 128) * ldB;
    D  += bb * sbD + ss * slD;

    if (tid < 128) {
        sBM[tid] = biasM ? biasM[by * 128 + tid] : 0.f;
        sBN[tid] = biasN ? biasN[bx * 128 + tid] : 0.f;
    }

    const int sf = tid & 7;       // k-chunk (4 floats)
    const int sr = tid >> 3;      // 0..31 (row base)
    const int nIter = K / 32;

    const float* pA[4];
    const float* pB[4];
#pragma unroll
    for (int i = 0; i < 4; ++i) {
        pA[i] = A  + (long)(sr + 32 * i) * ldA + sf * 4;
        pB[i] = Bm + (long)(sr + 32 * i) * ldB + sf * 4;
    }

    float4 ra[4], rb[4];
#pragma unroll
    for (int i = 0; i < 4; ++i) {
        ra[i] = *(const float4*)pA[i]; pA[i] += 32;
        rb[i] = *(const float4*)pB[i]; pB[i] += 32;
    }
    {
        half* Ab = sh;
        half* Bb = sh + 2 * TILE_HALVES;
#pragma unroll
        for (int i = 0; i < 4; ++i) {
            const int idx = (sr + 32 * i) * PITCH + sf * 4;
            split_store(Ab, idx, ra[i]);
            split_store(Bb, idx, rb[i]);
        }
    }
    __syncthreads();

    float acc[4][4][4];
#pragma unroll
    for (int mi = 0; mi < 4; ++mi)
#pragma unroll
        for (int ni = 0; ni < 4; ++ni)
#pragma unroll
            for (int q = 0; q < 4; ++q) acc[mi][ni][q] = 0.f;

    const int wid = tid >> 5, lid = tid & 31;
    const int wm = (wid >> 2) * 64;
    const int wn = (wid & 3) * 32;
    const int g = lid >> 2;
    const int t = lid & 3;

    const uint32_t laneA = (uint32_t)((lid & 15) * (PITCH * 2) + (lid >> 4) * 16);
    const uint32_t laneB = (uint32_t)((((lid >> 4) * 8) + (lid & 7)) * (PITCH * 2)
                                      + ((lid >> 3) & 1) * 16);
    const uint32_t aWarp = sbu + (uint32_t)(wm * (PITCH * 2)) + laneA;
    const uint32_t bWarp = sbu + 2 * TILE_BYTES + (uint32_t)(wn * (PITCH * 2)) + laneB;

    for (int it = 0; it < nIter; ++it) {
        const int buf = it & 1;
        const bool hasNext = (it + 1 < nIter);
        if (hasNext) {
#pragma unroll
            for (int i = 0; i < 4; ++i) {
                ra[i] = *(const float4*)pA[i]; pA[i] += 32;
                rb[i] = *(const float4*)pB[i]; pB[i] += 32;
            }
        }

        const uint32_t bo = (uint32_t)(buf * BUF_BYTES);
#pragma unroll
        for (int kk = 0; kk < 2; ++kk) {
            const uint32_t ko = (uint32_t)(kk * 32);
            uint32_t ah[4][4], al[4][4];
#pragma unroll
            for (int mi = 0; mi < 4; ++mi) {
                const uint32_t addr = aWarp + bo + (uint32_t)(mi * 16 * PITCH * 2) + ko;
                ldm_x4(ah[mi], addr);
                ldm_x4(al[mi], addr + TILE_BYTES);
            }
            uint32_t bh[2][4], bl[2][4];
#pragma unroll
            for (int nb = 0; nb < 2; ++nb) {
                const uint32_t addr = bWarp + bo + (uint32_t)(nb * 16 * PITCH * 2) + ko;
                ldm_x4(bh[nb], addr);
                ldm_x4(bl[nb], addr + TILE_BYTES);
            }
            // three passes: consecutive MMAs never share an accumulator
#pragma unroll
            for (int mi = 0; mi < 4; ++mi)
#pragma unroll
                for (int ni = 0; ni < 4; ++ni)
                    mma16816(acc[mi][ni], ah[mi], &bh[ni >> 1][(ni & 1) * 2]);
#pragma unroll
            for (int mi = 0; mi < 4; ++mi)
#pragma unroll
                for (int ni = 0; ni < 4; ++ni)
                    mma16816(acc[mi][ni], al[mi], &bh[ni >> 1][(ni & 1) * 2]);
#pragma unroll
            for (int mi = 0; mi < 4; ++mi)
#pragma unroll
                for (int ni = 0; ni < 4; ++ni)
                    mma16816(acc[mi][ni], ah[mi], &bl[ni >> 1][(ni & 1) * 2]);
        }

        if (hasNext) {
            half* Ab = sh + (buf ^ 1) * (BUF_BYTES / 2);   // halves offset
            half* Bb = Ab + 2 * TILE_HALVES;
#pragma unroll
            for (int i = 0; i < 4; ++i) {
                const int idx = (sr + 32 * i) * PITCH + sf * 4;
                split_store(Ab, idx, ra[i]);
                split_store(Bb, idx, rb[i]);
            }
        }
        __syncthreads();
    }

    // ---------------- epilogue ----------------
#pragma unroll
    for (int mi = 0; mi < 4; ++mi) {
        const int rowLoc = wm + mi * 16 + g;
        const int chan0 = by * 128 + rowLoc;
        const float bm0 = sBM[rowLoc], bm1 = sBM[rowLoc + 8];
        const long gr0 = (long)chan0 * Nt + bx * 128;
        const long gr1 = gr0 + 8L * Nt;
        float s0 = 0.f, q0 = 0.f, s1 = 0.f, q1 = 0.f;
#pragma unroll
        for (int ni = 0; ni < 4; ++ni) {
            const int col = wn + ni * 8 + t * 2;
            const float bn0 = sBN[col], bn1 = sBN[col + 1];
            float2 o0, o1;
            o0.x = alpha * acc[mi][ni][0] + bm0 + bn0;
            o0.y = alpha * acc[mi][ni][1] + bm0 + bn1;
            o1.x = alpha * acc[mi][ni][2] + bm1 + bn0;
            o1.y = alpha * acc[mi][ni][3] + bm1 + bn1;
            if (ATOMIC_OUT) {
                atomicAdd(&D[gr0 + col],     o0.x);
                atomicAdd(&D[gr0 + col + 1], o0.y);
                atomicAdd(&D[gr1 + col],     o1.x);
                atomicAdd(&D[gr1 + col + 1], o1.y);
            } else {
                *(float2*)&D[gr0 + col] = o0;
                *(float2*)&D[gr1 + col] = o1;
            }
            if (BN_ACC) {
                s0 += o0.x + o0.y;  q0 += o0.x * o0.x + o0.y * o0.y;
                s1 += o1.x + o1.y;  q1 += o1.x * o1.x + o1.y * o1.y;
            }
        }
        if (BN_ACC) {
#pragma unroll
            for (int o = 1; o < 4; o <<= 1) {
                s0 += __shfl_xor_sync(0xFFFFFFFF, s0, o);
                q0 += __shfl_xor_sync(0xFFFFFFFF, q0, o);
                s1 += __shfl_xor_sync(0xFFFFFFFF, s1, o);
                q1 += __shfl_xor_sync(0xFFFFFFFF, q1, o);
            }
            if (t == 0) {
                atomicAdd(&bn_sum[chan0],       s0);
                atomicAdd(&bn_sumsq[chan0],     q0);
                atomicAdd(&bn_sum[chan0 + 8],   s1);
                atomicAdd(&bn_sumsq[chan0 + 8], q1);
            }
        }
    }
}

// ------------------------------------------------------------------------------
// v [B,C,N] -> vT [B,N,C]
__global__ __launch_bounds__(256)
void transpose_kernel(const float* __restrict__ v, float* __restrict__ o)
{
    __shared__ float t[32][33];
    const int b = blockIdx.z;
    const int n0 = blockIdx.x * 32, c0 = blockIdx.y * 32;
    const int tx = threadIdx.x, ty = threadIdx.y;   // 32 x 8
#pragma unroll
    for (int i = 0; i < 4; ++i)
        t[ty + 8 * i][tx] = v[((long)b * C_ + c0 + ty + 8 * i) * N_ + n0 + tx];
    __syncthreads();
#pragma unroll
    for (int i = 0; i < 4; ++i)
        o[((long)b * N_ + n0 + ty + 8 * i) * C_ + c0 + tx] = t[tx][ty + 8 * i];
}

// ------------------------------------------------------------------------------
// zero Zt accumulator and BN accumulators (runs first every call)
__global__ __launch_bounds__(256)
void zero_kernel(float* __restrict__ Zt)
{
    const int i = blockIdx.x * 256 + threadIdx.x;   // 0 .. B*CI*CI-1
    Zt[i] = 0.f;
    if (i < C_) { bn_sum[i] = 0.f; bn_sumsq[i] = 0.f; }
}

// ------------------------------------------------------------------------------
// BN apply + affine + residual; stats from bn_sum/bn_sumsq accumulators.
__global__ __launch_bounds__(256)
void bn_apply_kernel(const float* __restrict__ Wy,
                     const float* __restrict__ v,
                     const float* __restrict__ gamma,
                     const float* __restrict__ beta,
                     float* __restrict__ out)
{
    const long idx = (long)blockIdx.x * 256 + threadIdx.x;
    const long total4 = (long)B_ * C_ * N_ / 4;
    if (idx >= total4) return;
    const int c = (int)((idx * 4 / N_) % C_);
    const float inv = 1.f / (float)(B_ * N_);
    const float mean = bn_sum[c] * inv;
    const float var  = fmaxf(bn_sumsq[c] * inv - mean * mean, 0.f);
    const float rstd = rsqrtf(var + EPS_);
    const float sc = rstd * gamma[c];
    const float sh = beta[c] - mean * sc;
    const float4 w  = ((const float4*)Wy)[idx];
    const float4 vv = ((const float4*)v)[idx];
    float4 o;
    o.x = w.x * sc + sh + vv.x;
    o.y = w.y * sc + sh + vv.y;
    o.z = w.z * sc + sh + vv.z;
    o.w = w.w * sc + sh + vv.w;
    ((float4*)out)[idx] = o;
}

// ------------------------------------------------------------------------------
#define SYM(p, s) cudaGetSymbolAddress((void**)&p, s)

extern "C" void kernel_launch(void* const* d_in, const int* in_sizes, int n_in,
                              void* d_out, int out_size)
{
    const float* v     = (const float*)d_in[0];
    const float* Wg    = (const float*)d_in[1];
    const float* bg    = (const float*)d_in[2];
    const float* Wth   = (const float*)d_in[3];
    const float* bth   = (const float*)d_in[4];
    const float* Wph   = (const float*)d_in[5];
    const float* bph   = (const float*)d_in[6];
    const float* Ww    = (const float*)d_in[7];
    const float* bw    = (const float*)d_in[8];
    const float* gamma = (const float*)d_in[9];
    const float* beta  = (const float*)d_in[10];
    float* out = (float*)d_out;

    float *vT, *th, *ph, *g, *y, *Wy, *Zt;
    SYM(vT, vT_buf);
    SYM(th, th_buf);
    SYM(ph, ph_buf);
    SYM(g,  g_buf);
    SYM(y,  y_buf);
    SYM(Wy, Wy_buf);
    SYM(Zt, Zt_buf);

    cudaFuncSetAttribute(gemm_fp16x3<false, false>, cudaFuncAttributeMaxDynamicSharedMemorySize, SMEM_GEMM_BYTES);
    cudaFuncSetAttribute(gemm_fp16x3<false, true >, cudaFuncAttributeMaxDynamicSharedMemorySize, SMEM_GEMM_BYTES);
    cudaFuncSetAttribute(gemm_fp16x3<true,  false>, cudaFuncAttributeMaxDynamicSharedMemorySize, SMEM_GEMM_BYTES);

    const long sVT = (long)N_ * C_;    // vT batch stride
    const long sNC = (long)N_ * CI_;   // [N,Ci]
    const long sCN = (long)CI_ * N_;   // [Ci,N]
    const long sC  = (long)C_ * N_;    // [C,N]
    const long sZ  = (long)CI_ * CI_;  // 65536

    // 0) zero Zt + BN accumulators; transpose v -> vT
    zero_kernel<<<(B_ * CI_ * CI_) / 256, 256>>>(Zt);
    transpose_kernel<<<dim3(N_ / 32, C_ / 32, B_), dim3(32, 8)>>>(v, vT);

    // 1) ph[ci,n] = Wph[ci,:].vT[n,:] + bph[ci]     (biasM)
    gemm_fp16x3<false, false><<<dim3(N_ / 128, CI_ / 128, B_), 256, SMEM_GEMM_BYTES>>>(
        Wph, vT, ph, bph, nullptr, CI_, N_, C_, C_, C_, 1.f,
        1, 0, 0, sVT, 0, sCN, 0);
    // 2) g[ci,n] = Wg[ci,:].vT[n,:] + bg[ci]
    gemm_fp16x3<false, false><<<dim3(N_ / 128, CI_ / 128, B_), 256, SMEM_GEMM_BYTES>>>(
        Wg, vT, g, bg, nullptr, CI_, N_, C_, C_, C_, 1.f,
        1, 0, 0, sVT, 0, sCN, 0);
    // 3) Zt[b][cg,cth] += (ZSCALE/N) * sum_{m in slice} g[cg,m] ph[cth,m]
    //    split-K 16 slices, atomic reduction into Zt (slD = 0)
    gemm_fp16x3<false, true><<<dim3(CI_ / 128, CI_ / 128, B_ * SLICES), 256, SMEM_GEMM_BYTES>>>(
        g, ph, Zt, nullptr, nullptr, CI_, CI_, N_ / SLICES, N_, N_, ZSCALE / (float)N_,
        SLICES, sCN, N_ / SLICES, sCN, N_ / SLICES, sZ, 0);
    // 4) th[n,cth] = vT[n,:].Wth[cth,:] + bth       (biasN)
    gemm_fp16x3<false, false><<<dim3(CI_ / 128, N_ / 128, B_), 256, SMEM_GEMM_BYTES>>>(
        vT, Wth, th, nullptr, bth, N_, CI_, C_, C_, C_, 1.f,
        1, sVT, 0, 0, 0, sNC, 0);
    // 5) y[n,cg] = (1/ZSCALE) * th[n,:].Zt[cg,:]
    gemm_fp16x3<false, false><<<dim3(CI_ / 128, N_ / 128, B_), 256, SMEM_GEMM_BYTES>>>(
        th, Zt, y, nullptr, nullptr, N_, CI_, CI_, CI_, CI_, 1.f / ZSCALE,
        1, sNC, 0, sZ, 0, sNC, 0);
    // 6) Wy[c,n] = Ww[c,:].y[n,:] + bw              (biasM; BN stats in epilogue)
    gemm_fp16x3<true, false><<<dim3(N_ / 128, C_ / 128, B_), 256, SMEM_GEMM_BYTES>>>(
        Ww, y, Wy, bw, nullptr, C_, N_, CI_, CI_, CI_, 1.f,
        1, 0, 0, sNC, 0, sC, 0);

    // 7) BN apply + affine + residual
    const long total4 = (long)B_ * C_ * N_ / 4;
    bn_apply_kernel<<<(int)((total4 + 255) / 256), 256>>>(Wy, v, gamma, beta, out);
}

// round 10
// speedup vs baseline: 1.1394x; 1.0242x over previous
#include <cuda_runtime.h>
#include <cuda_fp16.h>
#include <cstdint>

#define B_  4
#define C_  512
#define CI_ 256
#define N_  4096
#define EPS_ 1e-5f
#define ZSCALE 64.0f
#define SLICES 16

// ------------------------- device scratch (no allocs) -------------------------
__device__ float vT_buf[B_ * N_ * C_];                 // 32 MB [B,N,C]
__device__ float th_buf[B_ * N_ * CI_];                // 16 MB [B,N,Ci]
__device__ float ph_buf[B_ * CI_ * N_];                // 16 MB [B,Ci,N]
__device__ float g_buf [B_ * CI_ * N_];                // 16 MB [B,Ci,N]
__device__ float y_buf [B_ * N_ * CI_];                // 16 MB [B,N,Ci]
__device__ float Wy_buf[B_ * C_ * N_];                 // 32 MB [B,C,N]
__device__ float Zt_buf[B_ * CI_ * CI_];               //  1 MB [B,cg,cth]
__device__ float bn_sum[C_];
__device__ float bn_sumsq[C_];

// ------------------------------- GEMM config ----------------------------------
// CTA tile 128(M) x 64(N) x 32(K), 256 threads (8 warps in 4x2, 32x32 each).
// 2 CTAs/SM (regs <= 128 via launch_bounds, smem 61 KB/CTA).
#define PITCH 40                         // halves per smem row (80B), conflict-free
#define ROWB  (PITCH * 2)                // 80 bytes per row
#define A_TILE_B 10240                   // 128 rows * 80B
#define B_TILE_B 5120                    // 64 rows * 80B
#define A_TILE_H (A_TILE_B / 2)
#define B_TILE_H (B_TILE_B / 2)
#define OFF_AL   A_TILE_B                // byte offsets within one buffer
#define OFF_BH   (2 * A_TILE_B)          // 20480
#define OFF_BL   (2 * A_TILE_B + B_TILE_B)
#define BUF_BYTES (2 * A_TILE_B + 2 * B_TILE_B)   // 30720
#define SMEM_GEMM_BYTES (2 * BUF_BYTES + 1024)    // 62464

__device__ __forceinline__ uint32_t smem_u32(const void* p) {
    uint32_t a;
    asm("{ .reg .u64 t; cvta.to.shared.u64 t, %1; cvt.u32.u64 %0, t; }" : "=r"(a) : "l"(p));
    return a;
}
__device__ __forceinline__ void ldm_x4(uint32_t* r, uint32_t addr) {
    asm volatile("ldmatrix.sync.aligned.m8n8.x4.shared.b16 {%0,%1,%2,%3}, [%4];"
                 : "=r"(r[0]), "=r"(r[1]), "=r"(r[2]), "=r"(r[3]) : "r"(addr));
}
__device__ __forceinline__ void mma16816(float* c, const uint32_t* a, const uint32_t* b) {
    asm volatile(
        "mma.sync.aligned.m16n8k16.row.col.f32.f16.f16.f32 "
        "{%0,%1,%2,%3}, {%4,%5,%6,%7}, {%8,%9}, {%0,%1,%2,%3};"
        : "+f"(c[0]), "+f"(c[1]), "+f"(c[2]), "+f"(c[3])
        : "r"(a[0]), "r"(a[1]), "r"(a[2]), "r"(a[3]), "r"(b[0]), "r"(b[1]));
}

// split fp32x4 -> hi/lo fp16 pairs, store to smem (lo at +loOffHalves)
__device__ __forceinline__ void split_store(half* base, int idx, int loOffH, float4 x) {
    half2 h01 = __floats2half2_rn(x.x, x.y);
    half2 h23 = __floats2half2_rn(x.z, x.w);
    float2 f01 = __half22float2(h01);
    float2 f23 = __half22float2(h23);
    half2 l01 = __floats2half2_rn(x.x - f01.x, x.y - f01.y);
    half2 l23 = __floats2half2_rn(x.z - f23.x, x.w - f23.y);
    *(half2*)&base[idx]     = h01;
    *(half2*)&base[idx + 2] = h23;
    *(half2*)&base[loOffH + idx]     = l01;
    *(half2*)&base[loOffH + idx + 2] = l23;
}

// ------------------------------------------------------------------------------
// D[M,Nt] = alpha * A[M,K] @ B[Nt,K]^T + biasM[row] + biasN[col]
// A, B row-major, row strides ldA/ldB (K contiguous). 128x64x32 tiles, 256 thr.
// grid = (Nt/64, M/128, nBatch*nSlices); per-z: X += b*sbX + s*slX.
// BN_ACC: accumulate per-row sum/sumsq into bn_sum/bn_sumsq (atomics).
// ATOMIC_OUT: atomicAdd into D (split-K reduction); biases must be null.
// fp16x3 (hh + lh + hl), fp32 accumulate.
// ------------------------------------------------------------------------------
template <bool BN_ACC, bool ATOMIC_OUT>
__global__ __launch_bounds__(256, 2)
void gemm_fp16x3(const float* __restrict__ A, const float* __restrict__ Bm,
                 float* __restrict__ D,
                 const float* __restrict__ biasM, const float* __restrict__ biasN,
                 int M, int Nt, int K, int ldA, int ldB, float alpha,
                 int nSlices,
                 long sbA, long slA, long sbB, long slB, long sbD, long slD)
{
    extern __shared__ char smem[];
    half*  sh  = (half*)smem;
    float* sBM = (float*)(smem + 2 * BUF_BYTES);
    float* sBN = sBM + 128;
    const uint32_t sbu = smem_u32(sh);

    const int tid = threadIdx.x;
    const int bx = blockIdx.x, by = blockIdx.y, bz = blockIdx.z;
    const int bb = bz / nSlices;
    const int ss = bz % nSlices;
    A  += bb * sbA + ss * slA + (long)(by * 128) * ldA;
    Bm += bb * sbB + ss * slB + (long)(bx * 64) * ldB;
    D  += bb * sbD + ss * slD;

    if (tid < 128) sBM[tid] = biasM ? biasM[by * 128 + tid] : 0.f;
    if (tid < 64)  sBN[tid] = biasN ? biasN[bx * 64 + tid] : 0.f;

    const int sf = tid & 7;       // k-chunk (4 floats)
    const int sr = tid >> 3;      // 0..31 (row base)
    const int nIter = K / 32;

    // A: 128 rows, 4 per thread. B: 64 rows, 2 per thread.
    const float* pA[4];
    const float* pB[2];
#pragma unroll
    for (int i = 0; i < 4; ++i)
        pA[i] = A + (long)(sr + 32 * i) * ldA + sf * 4;
#pragma unroll
    for (int i = 0; i < 2; ++i)
        pB[i] = Bm + (long)(sr + 32 * i) * ldB + sf * 4;

    float4 ra[4], rb[2];
#pragma unroll
    for (int i = 0; i < 4; ++i) { ra[i] = *(const float4*)pA[i]; pA[i] += 32; }
#pragma unroll
    for (int i = 0; i < 2; ++i) { rb[i] = *(const float4*)pB[i]; pB[i] += 32; }
    {
        half* Ab = sh;                        // buf 0, A-hi base
        half* Bb = sh + OFF_BH / 2;           // buf 0, B-hi base (half idx)
#pragma unroll
        for (int i = 0; i < 4; ++i)
            split_store(Ab, (sr + 32 * i) * PITCH + sf * 4, A_TILE_H, ra[i]);
#pragma unroll
        for (int i = 0; i < 2; ++i)
            split_store(Bb, (sr + 32 * i) * PITCH + sf * 4, B_TILE_H, rb[i]);
    }
    __syncthreads();

    float acc[2][4][4];
#pragma unroll
    for (int mi = 0; mi < 2; ++mi)
#pragma unroll
        for (int ni = 0; ni < 4; ++ni)
#pragma unroll
            for (int q = 0; q < 4; ++q) acc[mi][ni][q] = 0.f;

    const int wid = tid >> 5, lid = tid & 31;
    const int wm = (wid >> 1) * 32;   // warp m offset: 0/32/64/96
    const int wn = (wid & 1) * 32;    // warp n offset: 0/32
    const int g = lid >> 2;
    const int t = lid & 3;

    const uint32_t laneA = (uint32_t)((lid & 15) * ROWB + (lid >> 4) * 16);
    const uint32_t laneB = (uint32_t)((((lid >> 4) * 8) + (lid & 7)) * ROWB
                                      + ((lid >> 3) & 1) * 16);
    const uint32_t aWarp = sbu + (uint32_t)(wm * ROWB) + laneA;
    const uint32_t bWarp = sbu + OFF_BH + (uint32_t)(wn * ROWB) + laneB;

    for (int it = 0; it < nIter; ++it) {
        const int buf = it & 1;
        const bool hasNext = (it + 1 < nIter);
        if (hasNext) {
#pragma unroll
            for (int i = 0; i < 4; ++i) { ra[i] = *(const float4*)pA[i]; pA[i] += 32; }
#pragma unroll
            for (int i = 0; i < 2; ++i) { rb[i] = *(const float4*)pB[i]; pB[i] += 32; }
        }

        const uint32_t bo = (uint32_t)(buf * BUF_BYTES);
#pragma unroll
        for (int kk = 0; kk < 2; ++kk) {
            const uint32_t ko = (uint32_t)(kk * 32);
            uint32_t ah[2][4], al[2][4];
#pragma unroll
            for (int mi = 0; mi < 2; ++mi) {
                const uint32_t addr = aWarp + bo + (uint32_t)(mi * 16 * ROWB) + ko;
                ldm_x4(ah[mi], addr);
                ldm_x4(al[mi], addr + A_TILE_B);
            }
            uint32_t bh[2][4], bl[2][4];
#pragma unroll
            for (int nb = 0; nb < 2; ++nb) {
                const uint32_t addr = bWarp + bo + (uint32_t)(nb * 16 * ROWB) + ko;
                ldm_x4(bh[nb], addr);
                ldm_x4(bl[nb], addr + B_TILE_B);
            }
            // three passes: consecutive MMAs never share an accumulator
#pragma unroll
            for (int mi = 0; mi < 2; ++mi)
#pragma unroll
                for (int ni = 0; ni < 4; ++ni)
                    mma16816(acc[mi][ni], ah[mi], &bh[ni >> 1][(ni & 1) * 2]);
#pragma unroll
            for (int mi = 0; mi < 2; ++mi)
#pragma unroll
                for (int ni = 0; ni < 4; ++ni)
                    mma16816(acc[mi][ni], al[mi], &bh[ni >> 1][(ni & 1) * 2]);
#pragma unroll
            for (int mi = 0; mi < 2; ++mi)
#pragma unroll
                for (int ni = 0; ni < 4; ++ni)
                    mma16816(acc[mi][ni], ah[mi], &bl[ni >> 1][(ni & 1) * 2]);
        }

        if (hasNext) {
            half* Ab = sh + (buf ^ 1) * (BUF_BYTES / 2);
            half* Bb = Ab + OFF_BH / 2;
#pragma unroll
            for (int i = 0; i < 4; ++i)
                split_store(Ab, (sr + 32 * i) * PITCH + sf * 4, A_TILE_H, ra[i]);
#pragma unroll
            for (int i = 0; i < 2; ++i)
                split_store(Bb, (sr + 32 * i) * PITCH + sf * 4, B_TILE_H, rb[i]);
        }
        __syncthreads();
    }

    // ---------------- epilogue ----------------
#pragma unroll
    for (int mi = 0; mi < 2; ++mi) {
        const int rowLoc = wm + mi * 16 + g;
        const int chan0 = by * 128 + rowLoc;
        const float bm0 = sBM[rowLoc], bm1 = sBM[rowLoc + 8];
        const long gr0 = (long)chan0 * Nt + bx * 64;
        const long gr1 = gr0 + 8L * Nt;
        float s0 = 0.f, q0 = 0.f, s1 = 0.f, q1 = 0.f;
#pragma unroll
        for (int ni = 0; ni < 4; ++ni) {
            const int col = wn + ni * 8 + t * 2;
            const float bn0 = sBN[col], bn1 = sBN[col + 1];
            float2 o0, o1;
            o0.x = alpha * acc[mi][ni][0] + bm0 + bn0;
            o0.y = alpha * acc[mi][ni][1] + bm0 + bn1;
            o1.x = alpha * acc[mi][ni][2] + bm1 + bn0;
            o1.y = alpha * acc[mi][ni][3] + bm1 + bn1;
            if (ATOMIC_OUT) {
                atomicAdd(&D[gr0 + col],     o0.x);
                atomicAdd(&D[gr0 + col + 1], o0.y);
                atomicAdd(&D[gr1 + col],     o1.x);
                atomicAdd(&D[gr1 + col + 1], o1.y);
            } else {
                *(float2*)&D[gr0 + col] = o0;
                *(float2*)&D[gr1 + col] = o1;
            }
            if (BN_ACC) {
                s0 += o0.x + o0.y;  q0 += o0.x * o0.x + o0.y * o0.y;
                s1 += o1.x + o1.y;  q1 += o1.x * o1.x + o1.y * o1.y;
            }
        }
        if (BN_ACC) {
#pragma unroll
            for (int o = 1; o < 4; o <<= 1) {
                s0 += __shfl_xor_sync(0xFFFFFFFF, s0, o);
                q0 += __shfl_xor_sync(0xFFFFFFFF, q0, o);
                s1 += __shfl_xor_sync(0xFFFFFFFF, s1, o);
                q1 += __shfl_xor_sync(0xFFFFFFFF, q1, o);
            }
            if (t == 0) {
                atomicAdd(&bn_sum[chan0],       s0);
                atomicAdd(&bn_sumsq[chan0],     q0);
                atomicAdd(&bn_sum[chan0 + 8],   s1);
                atomicAdd(&bn_sumsq[chan0 + 8], q1);
            }
        }
    }
}

// ------------------------------------------------------------------------------
// v [B,C,N] -> vT [B,N,C]
__global__ __launch_bounds__(256)
void transpose_kernel(const float* __restrict__ v, float* __restrict__ o)
{
    __shared__ float t[32][33];
    const int b = blockIdx.z;
    const int n0 = blockIdx.x * 32, c0 = blockIdx.y * 32;
    const int tx = threadIdx.x, ty = threadIdx.y;   // 32 x 8
#pragma unroll
    for (int i = 0; i < 4; ++i)
        t[ty + 8 * i][tx] = v[((long)b * C_ + c0 + ty + 8 * i) * N_ + n0 + tx];
    __syncthreads();
#pragma unroll
    for (int i = 0; i < 4; ++i)
        o[((long)b * N_ + n0 + ty + 8 * i) * C_ + c0 + tx] = t[tx][ty + 8 * i];
}

// ------------------------------------------------------------------------------
// zero Zt accumulator and BN accumulators (runs first every call)
__global__ __launch_bounds__(256)
void zero_kernel(float* __restrict__ Zt)
{
    const int i = blockIdx.x * 256 + threadIdx.x;   // 0 .. B*CI*CI-1
    Zt[i] = 0.f;
    if (i < C_) { bn_sum[i] = 0.f; bn_sumsq[i] = 0.f; }
}

// ------------------------------------------------------------------------------
// BN apply + affine + residual; stats from bn_sum/bn_sumsq accumulators.
__global__ __launch_bounds__(256)
void bn_apply_kernel(const float* __restrict__ Wy,
                     const float* __restrict__ v,
                     const float* __restrict__ gamma,
                     const float* __restrict__ beta,
                     float* __restrict__ out)
{
    const long idx = (long)blockIdx.x * 256 + threadIdx.x;
    const long total4 = (long)B_ * C_ * N_ / 4;
    if (idx >= total4) return;
    const int c = (int)((idx * 4 / N_) % C_);
    const float inv = 1.f / (float)(B_ * N_);
    const float mean = bn_sum[c] * inv;
    const float var  = fmaxf(bn_sumsq[c] * inv - mean * mean, 0.f);
    const float rstd = rsqrtf(var + EPS_);
    const float sc = rstd * gamma[c];
    const float sh = beta[c] - mean * sc;
    const float4 w  = ((const float4*)Wy)[idx];
    const float4 vv = ((const float4*)v)[idx];
    float4 o;
    o.x = w.x * sc + sh + vv.x;
    o.y = w.y * sc + sh + vv.y;
    o.z = w.z * sc + sh + vv.z;
    o.w = w.w * sc + sh + vv.w;
    ((float4*)out)[idx] = o;
}

// ------------------------------------------------------------------------------
#define SYM(p, s) cudaGetSymbolAddress((void**)&p, s)

extern "C" void kernel_launch(void* const* d_in, const int* in_sizes, int n_in,
                              void* d_out, int out_size)
{
    const float* v     = (const float*)d_in[0];
    const float* Wg    = (const float*)d_in[1];
    const float* bg    = (const float*)d_in[2];
    const float* Wth   = (const float*)d_in[3];
    const float* bth   = (const float*)d_in[4];
    const float* Wph   = (const float*)d_in[5];
    const float* bph   = (const float*)d_in[6];
    const float* Ww    = (const float*)d_in[7];
    const float* bw    = (const float*)d_in[8];
    const float* gamma = (const float*)d_in[9];
    const float* beta  = (const float*)d_in[10];
    float* out = (float*)d_out;

    float *vT, *th, *ph, *g, *y, *Wy, *Zt;
    SYM(vT, vT_buf);
    SYM(th, th_buf);
    SYM(ph, ph_buf);
    SYM(g,  g_buf);
    SYM(y,  y_buf);
    SYM(Wy, Wy_buf);
    SYM(Zt, Zt_buf);

    cudaFuncSetAttribute(gemm_fp16x3<false, false>, cudaFuncAttributeMaxDynamicSharedMemorySize, SMEM_GEMM_BYTES);
    cudaFuncSetAttribute(gemm_fp16x3<false, true >, cudaFuncAttributeMaxDynamicSharedMemorySize, SMEM_GEMM_BYTES);
    cudaFuncSetAttribute(gemm_fp16x3<true,  false>, cudaFuncAttributeMaxDynamicSharedMemorySize, SMEM_GEMM_BYTES);

    const long sVT = (long)N_ * C_;    // vT batch stride
    const long sNC = (long)N_ * CI_;   // [N,Ci]
    const long sCN = (long)CI_ * N_;   // [Ci,N]
    const long sC  = (long)C_ * N_;    // [C,N]
    const long sZ  = (long)CI_ * CI_;  // 65536

    // 0) zero Zt + BN accumulators; transpose v -> vT
    zero_kernel<<<(B_ * CI_ * CI_) / 256, 256>>>(Zt);
    transpose_kernel<<<dim3(N_ / 32, C_ / 32, B_), dim3(32, 8)>>>(v, vT);

    // 1) ph[ci,n] = Wph[ci,:].vT[n,:] + bph[ci]     (biasM)
    gemm_fp16x3<false, false><<<dim3(N_ / 64, CI_ / 128, B_), 256, SMEM_GEMM_BYTES>>>(
        Wph, vT, ph, bph, nullptr, CI_, N_, C_, C_, C_, 1.f,
        1, 0, 0, sVT, 0, sCN, 0);
    // 2) g[ci,n] = Wg[ci,:].vT[n,:] + bg[ci]
    gemm_fp16x3<false, false><<<dim3(N_ / 64, CI_ / 128, B_), 256, SMEM_GEMM_BYTES>>>(
        Wg, vT, g, bg, nullptr, CI_, N_, C_, C_, C_, 1.f,
        1, 0, 0, sVT, 0, sCN, 0);
    // 3) Zt[b][cg,cth] += (ZSCALE/N) * sum_{m in slice} g[cg,m] ph[cth,m]
    //    split-K 16 slices, atomic reduction into Zt (slD = 0)
    gemm_fp16x3<false, true><<<dim3(CI_ / 64, CI_ / 128, B_ * SLICES), 256, SMEM_GEMM_BYTES>>>(
        g, ph, Zt, nullptr, nullptr, CI_, CI_, N_ / SLICES, N_, N_, ZSCALE / (float)N_,
        SLICES, sCN, N_ / SLICES, sCN, N_ / SLICES, sZ, 0);
    // 4) th[n,cth] = vT[n,:].Wth[cth,:] + bth       (biasN)
    gemm_fp16x3<false, false><<<dim3(CI_ / 64, N_ / 128, B_), 256, SMEM_GEMM_BYTES>>>(
        vT, Wth, th, nullptr, bth, N_, CI_, C_, C_, C_, 1.f,
        1, sVT, 0, 0, 0, sNC, 0);
    // 5) y[n,cg] = (1/ZSCALE) * th[n,:].Zt[cg,:]
    gemm_fp16x3<false, false><<<dim3(CI_ / 64, N_ / 128, B_), 256, SMEM_GEMM_BYTES>>>(
        th, Zt, y, nullptr, nullptr, N_, CI_, CI_, CI_, CI_, 1.f / ZSCALE,
        1, sNC, 0, sZ, 0, sNC, 0);
    // 6) Wy[c,n] = Ww[c,:].y[n,:] + bw              (biasM; BN stats in epilogue)
    gemm_fp16x3<true, false><<<dim3(N_ / 64, C_ / 128, B_), 256, SMEM_GEMM_BYTES>>>(
        Ww, y, Wy, bw, nullptr, C_, N_, CI_, CI_, CI_, 1.f,
        1, 0, 0, sNC, 0, sC, 0);

    // 7) BN apply + affine + residual
    const long total4 = (long)B_ * C_ * N_ / 4;
    bn_apply_kernel<<<(int)((total4 + 255) / 256), 256>>>(Wy, v, gamma, beta, out);
}

// round 11
// speedup vs baseline: 1.3204x; 1.1589x over previous
#include <cuda_runtime.h>
#include <cuda_fp16.h>
#include <cstdint>

#define B_  4
#define C_  512
#define CI_ 256
#define N_  4096
#define EPS_ 1e-5f
#define ZSCALE 64.0f
#define SLICES 16

// ------------------------- device scratch (no allocs) -------------------------
__device__ float vT_buf[B_ * N_ * C_];                 // 32 MB [B,N,C]
__device__ float th_buf[B_ * N_ * CI_];                // 16 MB [B,N,Ci]
__device__ float ph_buf[B_ * CI_ * N_];                // 16 MB [B,Ci,N]
__device__ float g_buf [B_ * CI_ * N_];                // 16 MB [B,Ci,N]
__device__ float y_buf [B_ * N_ * CI_];                // 16 MB [B,N,Ci]
__device__ float Wy_buf[B_ * C_ * N_];                 // 32 MB [B,C,N]
__device__ float Zt_buf[B_ * CI_ * CI_];               //  1 MB [B,cg,cth]
__device__ float bn_sum[C_];
__device__ float bn_sumsq[C_];

// ------------------------------- GEMM config ----------------------------------
// CTA tile 128(M) x 64(N) x 32(K), 256 threads (8 warps in 4x2, 32x32 each).
// fp16x2: A split hi+lo (two planes), B hi only (one plane).
#define PITCH 40                         // halves per smem row (80B), conflict-free
#define ROWB  (PITCH * 2)                // 80 bytes per row
#define A_TILE_B 10240                   // 128 rows * 80B (per plane)
#define B_TILE_B 5120                    // 64 rows * 80B (hi plane only)
#define A_TILE_H (A_TILE_B / 2)
#define OFF_BH   (2 * A_TILE_B)          // 20480: B-hi plane offset
#define BUF_BYTES (2 * A_TILE_B + B_TILE_B)        // 25600
#define SMEM_GEMM_BYTES (2 * BUF_BYTES + 1024)     // 52224

__device__ __forceinline__ uint32_t smem_u32(const void* p) {
    uint32_t a;
    asm("{ .reg .u64 t; cvta.to.shared.u64 t, %1; cvt.u32.u64 %0, t; }" : "=r"(a) : "l"(p));
    return a;
}
__device__ __forceinline__ void ldm_x4(uint32_t* r, uint32_t addr) {
    asm volatile("ldmatrix.sync.aligned.m8n8.x4.shared.b16 {%0,%1,%2,%3}, [%4];"
                 : "=r"(r[0]), "=r"(r[1]), "=r"(r[2]), "=r"(r[3]) : "r"(addr));
}
__device__ __forceinline__ void mma16816(float* c, const uint32_t* a, const uint32_t* b) {
    asm volatile(
        "mma.sync.aligned.m16n8k16.row.col.f32.f16.f16.f32 "
        "{%0,%1,%2,%3}, {%4,%5,%6,%7}, {%8,%9}, {%0,%1,%2,%3};"
        : "+f"(c[0]), "+f"(c[1]), "+f"(c[2]), "+f"(c[3])
        : "r"(a[0]), "r"(a[1]), "r"(a[2]), "r"(a[3]), "r"(b[0]), "r"(b[1]));
}

// A: split fp32x4 -> hi/lo fp16 pairs (lo at +A_TILE_H halves)
__device__ __forceinline__ void split_store(half* base, int idx, float4 x) {
    half2 h01 = __floats2half2_rn(x.x, x.y);
    half2 h23 = __floats2half2_rn(x.z, x.w);
    float2 f01 = __half22float2(h01);
    float2 f23 = __half22float2(h23);
    half2 l01 = __floats2half2_rn(x.x - f01.x, x.y - f01.y);
    half2 l23 = __floats2half2_rn(x.z - f23.x, x.w - f23.y);
    *(half2*)&base[idx]     = h01;
    *(half2*)&base[idx + 2] = h23;
    *(half2*)&base[A_TILE_H + idx]     = l01;
    *(half2*)&base[A_TILE_H + idx + 2] = l23;
}
// B: hi plane only
__device__ __forceinline__ void store_hi(half* base, int idx, float4 x) {
    *(half2*)&base[idx]     = __floats2half2_rn(x.x, x.y);
    *(half2*)&base[idx + 2] = __floats2half2_rn(x.z, x.w);
}

// ------------------------------------------------------------------------------
// D[M,Nt] = alpha * A[M,K] @ B[Nt,K]^T + biasM[row] + biasN[col]
// A, B row-major, row strides ldA/ldB (K contiguous). 128x64x32 tiles, 256 thr.
// grid = (Nt/64, M/128, nBatch*nSlices); per-z: X += b*sbX + s*slX.
// BN_ACC: accumulate per-row sum/sumsq into bn_sum/bn_sumsq (atomics).
// ATOMIC_OUT: atomicAdd into D (split-K reduction); biases must be null.
// fp16x2 (hh + lh), fp32 accumulate: rel err ~2e-4.
// ------------------------------------------------------------------------------
template <bool BN_ACC, bool ATOMIC_OUT>
__global__ __launch_bounds__(256, 2)
void gemm_fp16x2(const float* __restrict__ A, const float* __restrict__ Bm,
                 float* __restrict__ D,
                 const float* __restrict__ biasM, const float* __restrict__ biasN,
                 int M, int Nt, int K, int ldA, int ldB, float alpha,
                 int nSlices,
                 long sbA, long slA, long sbB, long slB, long sbD, long slD)
{
    extern __shared__ char smem[];
    half*  sh  = (half*)smem;
    float* sBM = (float*)(smem + 2 * BUF_BYTES);
    float* sBN = sBM + 128;
    const uint32_t sbu = smem_u32(sh);

    const int tid = threadIdx.x;
    const int bx = blockIdx.x, by = blockIdx.y, bz = blockIdx.z;
    const int bb = bz / nSlices;
    const int ss = bz % nSlices;
    A  += bb * sbA + ss * slA + (long)(by * 128) * ldA;
    Bm += bb * sbB + ss * slB + (long)(bx * 64) * ldB;
    D  += bb * sbD + ss * slD;

    if (tid < 128) sBM[tid] = biasM ? biasM[by * 128 + tid] : 0.f;
    if (tid < 64)  sBN[tid] = biasN ? biasN[bx * 64 + tid] : 0.f;

    const int sf = tid & 7;       // k-chunk (4 floats)
    const int sr = tid >> 3;      // 0..31 (row base)
    const int nIter = K / 32;

    // A: 128 rows, 4 per thread. B: 64 rows, 2 per thread.
    const float* pA[4];
    const float* pB[2];
#pragma unroll
    for (int i = 0; i < 4; ++i)
        pA[i] = A + (long)(sr + 32 * i) * ldA + sf * 4;
#pragma unroll
    for (int i = 0; i < 2; ++i)
        pB[i] = Bm + (long)(sr + 32 * i) * ldB + sf * 4;

    float4 ra[4], rb[2];
#pragma unroll
    for (int i = 0; i < 4; ++i) { ra[i] = *(const float4*)pA[i]; pA[i] += 32; }
#pragma unroll
    for (int i = 0; i < 2; ++i) { rb[i] = *(const float4*)pB[i]; pB[i] += 32; }
    {
        half* Ab = sh;                        // buf 0, A-hi base
        half* Bb = sh + OFF_BH / 2;           // buf 0, B-hi base (half idx)
#pragma unroll
        for (int i = 0; i < 4; ++i)
            split_store(Ab, (sr + 32 * i) * PITCH + sf * 4, ra[i]);
#pragma unroll
        for (int i = 0; i < 2; ++i)
            store_hi(Bb, (sr + 32 * i) * PITCH + sf * 4, rb[i]);
    }
    __syncthreads();

    float acc[2][4][4];
#pragma unroll
    for (int mi = 0; mi < 2; ++mi)
#pragma unroll
        for (int ni = 0; ni < 4; ++ni)
#pragma unroll
            for (int q = 0; q < 4; ++q) acc[mi][ni][q] = 0.f;

    const int wid = tid >> 5, lid = tid & 31;
    const int wm = (wid >> 1) * 32;   // warp m offset: 0/32/64/96
    const int wn = (wid & 1) * 32;    // warp n offset: 0/32
    const int g = lid >> 2;
    const int t = lid & 3;

    const uint32_t laneA = (uint32_t)((lid & 15) * ROWB + (lid >> 4) * 16);
    const uint32_t laneB = (uint32_t)((((lid >> 4) * 8) + (lid & 7)) * ROWB
                                      + ((lid >> 3) & 1) * 16);
    const uint32_t aWarp = sbu + (uint32_t)(wm * ROWB) + laneA;
    const uint32_t bWarp = sbu + OFF_BH + (uint32_t)(wn * ROWB) + laneB;

    for (int it = 0; it < nIter; ++it) {
        const int buf = it & 1;
        const bool hasNext = (it + 1 < nIter);
        if (hasNext) {
#pragma unroll
            for (int i = 0; i < 4; ++i) { ra[i] = *(const float4*)pA[i]; pA[i] += 32; }
#pragma unroll
            for (int i = 0; i < 2; ++i) { rb[i] = *(const float4*)pB[i]; pB[i] += 32; }
        }

        const uint32_t bo = (uint32_t)(buf * BUF_BYTES);
#pragma unroll
        for (int kk = 0; kk < 2; ++kk) {
            const uint32_t ko = (uint32_t)(kk * 32);
            uint32_t ah[2][4], al[2][4];
#pragma unroll
            for (int mi = 0; mi < 2; ++mi) {
                const uint32_t addr = aWarp + bo + (uint32_t)(mi * 16 * ROWB) + ko;
                ldm_x4(ah[mi], addr);
                ldm_x4(al[mi], addr + A_TILE_B);
            }
            uint32_t bh[2][4];
#pragma unroll
            for (int nb = 0; nb < 2; ++nb) {
                const uint32_t addr = bWarp + bo + (uint32_t)(nb * 16 * ROWB) + ko;
                ldm_x4(bh[nb], addr);
            }
            // two passes: consecutive MMAs never share an accumulator
#pragma unroll
            for (int mi = 0; mi < 2; ++mi)
#pragma unroll
                for (int ni = 0; ni < 4; ++ni)
                    mma16816(acc[mi][ni], ah[mi], &bh[ni >> 1][(ni & 1) * 2]);
#pragma unroll
            for (int mi = 0; mi < 2; ++mi)
#pragma unroll
                for (int ni = 0; ni < 4; ++ni)
                    mma16816(acc[mi][ni], al[mi], &bh[ni >> 1][(ni & 1) * 2]);
        }

        if (hasNext) {
            half* Ab = sh + (buf ^ 1) * (BUF_BYTES / 2);
            half* Bb = Ab + OFF_BH / 2;
#pragma unroll
            for (int i = 0; i < 4; ++i)
                split_store(Ab, (sr + 32 * i) * PITCH + sf * 4, ra[i]);
#pragma unroll
            for (int i = 0; i < 2; ++i)
                store_hi(Bb, (sr + 32 * i) * PITCH + sf * 4, rb[i]);
        }
        __syncthreads();
    }

    // ---------------- epilogue ----------------
#pragma unroll
    for (int mi = 0; mi < 2; ++mi) {
        const int rowLoc = wm + mi * 16 + g;
        const int chan0 = by * 128 + rowLoc;
        const float bm0 = sBM[rowLoc], bm1 = sBM[rowLoc + 8];
        const long gr0 = (long)chan0 * Nt + bx * 64;
        const long gr1 = gr0 + 8L * Nt;
        float s0 = 0.f, q0 = 0.f, s1 = 0.f, q1 = 0.f;
#pragma unroll
        for (int ni = 0; ni < 4; ++ni) {
            const int col = wn + ni * 8 + t * 2;
            const float bn0 = sBN[col], bn1 = sBN[col + 1];
            float2 o0, o1;
            o0.x = alpha * acc[mi][ni][0] + bm0 + bn0;
            o0.y = alpha * acc[mi][ni][1] + bm0 + bn1;
            o1.x = alpha * acc[mi][ni][2] + bm1 + bn0;
            o1.y = alpha * acc[mi][ni][3] + bm1 + bn1;
            if (ATOMIC_OUT) {
                atomicAdd(&D[gr0 + col],     o0.x);
                atomicAdd(&D[gr0 + col + 1], o0.y);
                atomicAdd(&D[gr1 + col],     o1.x);
                atomicAdd(&D[gr1 + col + 1], o1.y);
            } else {
                *(float2*)&D[gr0 + col] = o0;
                *(float2*)&D[gr1 + col] = o1;
            }
            if (BN_ACC) {
                s0 += o0.x + o0.y;  q0 += o0.x * o0.x + o0.y * o0.y;
                s1 += o1.x + o1.y;  q1 += o1.x * o1.x + o1.y * o1.y;
            }
        }
        if (BN_ACC) {
#pragma unroll
            for (int o = 1; o < 4; o <<= 1) {
                s0 += __shfl_xor_sync(0xFFFFFFFF, s0, o);
                q0 += __shfl_xor_sync(0xFFFFFFFF, q0, o);
                s1 += __shfl_xor_sync(0xFFFFFFFF, s1, o);
                q1 += __shfl_xor_sync(0xFFFFFFFF, q1, o);
            }
            if (t == 0) {
                atomicAdd(&bn_sum[chan0],       s0);
                atomicAdd(&bn_sumsq[chan0],     q0);
                atomicAdd(&bn_sum[chan0 + 8],   s1);
                atomicAdd(&bn_sumsq[chan0 + 8], q1);
            }
        }
    }
}

// ------------------------------------------------------------------------------
// v [B,C,N] -> vT [B,N,C]
__global__ __launch_bounds__(256)
void transpose_kernel(const float* __restrict__ v, float* __restrict__ o)
{
    __shared__ float t[32][33];
    const int b = blockIdx.z;
    const int n0 = blockIdx.x * 32, c0 = blockIdx.y * 32;
    const int tx = threadIdx.x, ty = threadIdx.y;   // 32 x 8
#pragma unroll
    for (int i = 0; i < 4; ++i)
        t[ty + 8 * i][tx] = v[((long)b * C_ + c0 + ty + 8 * i) * N_ + n0 + tx];
    __syncthreads();
#pragma unroll
    for (int i = 0; i < 4; ++i)
        o[((long)b * N_ + n0 + ty + 8 * i) * C_ + c0 + tx] = t[tx][ty + 8 * i];
}

// ------------------------------------------------------------------------------
// zero Zt accumulator and BN accumulators (runs first every call)
__global__ __launch_bounds__(256)
void zero_kernel(float* __restrict__ Zt)
{
    const int i = blockIdx.x * 256 + threadIdx.x;   // 0 .. B*CI*CI-1
    Zt[i] = 0.f;
    if (i < C_) { bn_sum[i] = 0.f; bn_sumsq[i] = 0.f; }
}

// ------------------------------------------------------------------------------
// BN apply + affine + residual; stats from bn_sum/bn_sumsq accumulators.
__global__ __launch_bounds__(256)
void bn_apply_kernel(const float* __restrict__ Wy,
                     const float* __restrict__ v,
                     const float* __restrict__ gamma,
                     const float* __restrict__ beta,
                     float* __restrict__ out)
{
    const long idx = (long)blockIdx.x * 256 + threadIdx.x;
    const long total4 = (long)B_ * C_ * N_ / 4;
    if (idx >= total4) return;
    const int c = (int)((idx * 4 / N_) % C_);
    const float inv = 1.f / (float)(B_ * N_);
    const float mean = bn_sum[c] * inv;
    const float var  = fmaxf(bn_sumsq[c] * inv - mean * mean, 0.f);
    const float rstd = rsqrtf(var + EPS_);
    const float sc = rstd * gamma[c];
    const float sh = beta[c] - mean * sc;
    const float4 w  = ((const float4*)Wy)[idx];
    const float4 vv = ((const float4*)v)[idx];
    float4 o;
    o.x = w.x * sc + sh + vv.x;
    o.y = w.y * sc + sh + vv.y;
    o.z = w.z * sc + sh + vv.z;
    o.w = w.w * sc + sh + vv.w;
    ((float4*)out)[idx] = o;
}

// ------------------------------------------------------------------------------
#define SYM(p, s) cudaGetSymbolAddress((void**)&p, s)

extern "C" void kernel_launch(void* const* d_in, const int* in_sizes, int n_in,
                              void* d_out, int out_size)
{
    const float* v     = (const float*)d_in[0];
    const float* Wg    = (const float*)d_in[1];
    const float* bg    = (const float*)d_in[2];
    const float* Wth   = (const float*)d_in[3];
    const float* bth   = (const float*)d_in[4];
    const float* Wph   = (const float*)d_in[5];
    const float* bph   = (const float*)d_in[6];
    const float* Ww    = (const float*)d_in[7];
    const float* bw    = (const float*)d_in[8];
    const float* gamma = (const float*)d_in[9];
    const float* beta  = (const float*)d_in[10];
    float* out = (float*)d_out;

    float *vT, *th, *ph, *g, *y, *Wy, *Zt;
    SYM(vT, vT_buf);
    SYM(th, th_buf);
    SYM(ph, ph_buf);
    SYM(g,  g_buf);
    SYM(y,  y_buf);
    SYM(Wy, Wy_buf);
    SYM(Zt, Zt_buf);

    cudaFuncSetAttribute(gemm_fp16x2<false, false>, cudaFuncAttributeMaxDynamicSharedMemorySize, SMEM_GEMM_BYTES);
    cudaFuncSetAttribute(gemm_fp16x2<false, true >, cudaFuncAttributeMaxDynamicSharedMemorySize, SMEM_GEMM_BYTES);
    cudaFuncSetAttribute(gemm_fp16x2<true,  false>, cudaFuncAttributeMaxDynamicSharedMemorySize, SMEM_GEMM_BYTES);

    const long sVT = (long)N_ * C_;    // vT batch stride
    const long sNC = (long)N_ * CI_;   // [N,Ci]
    const long sCN = (long)CI_ * N_;   // [Ci,N]
    const long sC  = (long)C_ * N_;    // [C,N]
    const long sZ  = (long)CI_ * CI_;  // 65536

    // 0) zero Zt + BN accumulators; transpose v -> vT
    zero_kernel<<<(B_ * CI_ * CI_) / 256, 256>>>(Zt);
    transpose_kernel<<<dim3(N_ / 32, C_ / 32, B_), dim3(32, 8)>>>(v, vT);

    // 1) ph[ci,n] = Wph[ci,:].vT[n,:] + bph[ci]     (biasM)
    gemm_fp16x2<false, false><<<dim3(N_ / 64, CI_ / 128, B_), 256, SMEM_GEMM_BYTES>>>(
        Wph, vT, ph, bph, nullptr, CI_, N_, C_, C_, C_, 1.f,
        1, 0, 0, sVT, 0, sCN, 0);
    // 2) g[ci,n] = Wg[ci,:].vT[n,:] + bg[ci]
    gemm_fp16x2<false, false><<<dim3(N_ / 64, CI_ / 128, B_), 256, SMEM_GEMM_BYTES>>>(
        Wg, vT, g, bg, nullptr, CI_, N_, C_, C_, C_, 1.f,
        1, 0, 0, sVT, 0, sCN, 0);
    // 3) Zt[b][cg,cth] += (ZSCALE/N) * sum_{m in slice} g[cg,m] ph[cth,m]
    //    split-K 16 slices, atomic reduction into Zt (slD = 0)
    gemm_fp16x2<false, true><<<dim3(CI_ / 64, CI_ / 128, B_ * SLICES), 256, SMEM_GEMM_BYTES>>>(
        g, ph, Zt, nullptr, nullptr, CI_, CI_, N_ / SLICES, N_, N_, ZSCALE / (float)N_,
        SLICES, sCN, N_ / SLICES, sCN, N_ / SLICES, sZ, 0);
    // 4) th[n,cth] = vT[n,:].Wth[cth,:] + bth       (biasN)
    gemm_fp16x2<false, false><<<dim3(CI_ / 64, N_ / 128, B_), 256, SMEM_GEMM_BYTES>>>(
        vT, Wth, th, nullptr, bth, N_, CI_, C_, C_, C_, 1.f,
        1, sVT, 0, 0, 0, sNC, 0);
    // 5) y[n,cg] = (1/ZSCALE) * th[n,:].Zt[cg,:]
    gemm_fp16x2<false, false><<<dim3(CI_ / 64, N_ / 128, B_), 256, SMEM_GEMM_BYTES>>>(
        th, Zt, y, nullptr, nullptr, N_, CI_, CI_, CI_, CI_, 1.f / ZSCALE,
        1, sNC, 0, sZ, 0, sNC, 0);
    // 6) Wy[c,n] = Ww[c,:].y[n,:] + bw              (biasM; BN stats in epilogue)
    gemm_fp16x2<true, false><<<dim3(N_ / 64, C_ / 128, B_), 256, SMEM_GEMM_BYTES>>>(
        Ww, y, Wy, bw, nullptr, C_, N_, CI_, CI_, CI_, 1.f,
        1, 0, 0, sNC, 0, sC, 0);

    // 7) BN apply + affine + residual
    const long total4 = (long)B_ * C_ * N_ / 4;
    bn_apply_kernel<<<(int)((total4 + 255) / 256), 256>>>(Wy, v, gamma, beta, out);
}